// round 13
// baseline (speedup 1.0000x reference)
#include <cuda_runtime.h>
#include <cuda_fp16.h>
#include <math.h>
#include <stdint.h>

// ---------------- problem constants ----------------
#define BATCH 8
#define SEQ   4096
#define DIM   512
#define HIDDEN 2048
#define ROWS  (BATCH*SEQ)           // 32768
#define SCALE 0.125f
#define LN_EPS 1e-5f
#define NSPLIT 8

// ---------------- scratch ----------------
__device__ __half g_curh[ROWS*DIM];
__device__ __half g_qkvh[ROWS*3*DIM];
__device__ float  g_spart[NSPLIT*64*64*64];
__device__ float  g_attnT[64*64*64];
__device__ __half g_attnouth[ROWS*DIM];
__device__ __half g_x1h[ROWS*DIM];
__device__ __half g_hh[ROWS*HIDDEN];
__device__ __half g_yh[ROWS*DIM];
__device__ float  g_pooled[BATCH*DIM];
__device__ float  g_gate[BATCH*DIM];
__device__ __half g_wqkvh[3*DIM*DIM];
__device__ __half g_wprojh[DIM*DIM];
__device__ __half g_wfc1h[HIDDEN*DIM];
__device__ __half g_wfc2h[DIM*HIDDEN];

// ================= helpers =================
__device__ __forceinline__ uint32_t smem_u32(const void* p) {
    uint32_t a;
    asm("{ .reg .u64 t; cvta.to.shared.u64 t, %1; cvt.u32.u64 %0, t; }" : "=r"(a) : "l"(p));
    return a;
}
__device__ __forceinline__ void cp_async16(uint32_t dst, const void* src) {
    asm volatile("cp.async.cg.shared.global [%0], [%1], 16;" :: "r"(dst), "l"(src) : "memory");
}
#define CP_COMMIT() asm volatile("cp.async.commit_group;" ::: "memory")
#define CP_WAIT(n)  asm volatile("cp.async.wait_group %0;" :: "n"(n) : "memory")

__device__ __forceinline__ void mma_f16(float* c, const uint32_t* a, const uint32_t* b) {
    asm volatile(
        "mma.sync.aligned.m16n8k16.row.col.f32.f16.f16.f32 "
        "{%0,%1,%2,%3}, {%4,%5,%6,%7}, {%8,%9}, {%0,%1,%2,%3};"
        : "+f"(c[0]), "+f"(c[1]), "+f"(c[2]), "+f"(c[3])
        : "r"(a[0]), "r"(a[1]), "r"(a[2]), "r"(a[3]), "r"(b[0]), "r"(b[1]));
}
__device__ __forceinline__ float gelu_f(float v) {
    return 0.5f * v * (1.f + erff(v * 0.70710678118f));
}

// ================= FP16 mma.sync GEMM =================
// C[m,n] = sum_k A[m,k] * W[n,k]   (+epilogue); all outputs fp16
// epi: 0 = no bias                 (qkv)
//      1 = +bias, pooled atomics   (fc2)
//      2 = +bias+gelu              (fc1)
//      3 = +bias+res(f32)          (proj -> x1h)
#define BM 128
#define BN 128
#define BKH 64                                  // halfs per chunk: 128B rows
#define NSTAGE 3
#define TILE_BYTES (BM*BKH*2)                   // 16KB
#define STAGE_BYTES (2*TILE_BYTES)              // 32KB (A+B)
#define GEMM_SMEM (NSTAGE*STAGE_BYTES)          // 96KB

__device__ __forceinline__ void load_tile_h(uint32_t dst, const __half* __restrict__ src,
                                            int K, int tid)
{
    int row = tid >> 3;       // 0..31
    int u   = tid & 7;        // 16B unit within 128B row
#pragma unroll
    for (int i = 0; i < 4; i++) {
        int r = row + i * 32;
        uint32_t soff = (uint32_t)(r * 8 + (u ^ (r & 7))) * 16;
        cp_async16(dst + soff, src + (size_t)r * K + u * 8);
    }
}

__global__ void __launch_bounds__(256, 2)
hgemm(const __half* __restrict__ A, const __half* __restrict__ W,
      __half* __restrict__ C, int M, int N, int K,
      const float* __restrict__ bias, const float* __restrict__ res,
      float* __restrict__ pooled, int epi)
{
    extern __shared__ __align__(16) char smem[];
    const int tid  = threadIdx.x;
    const int warp = tid >> 5, lane = tid & 31;
    const int lr = lane >> 2, lc = lane & 3;
    const int wm = warp & 1, wn = warp >> 1;      // 2 x 4 warp grid
    const int bm = blockIdx.y * BM, bn = blockIdx.x * BN;
    const int nch = K / BKH;

    const __half* Ablk = A + (size_t)bm * K;
    const __half* Wblk = W + (size_t)bn * K;

    float acc[4][4][4];
#pragma unroll
    for (int i = 0; i < 4; i++)
#pragma unroll
        for (int j = 0; j < 4; j++)
#pragma unroll
            for (int q = 0; q < 4; q++) acc[i][j][q] = 0.f;

    // prologue: stages 0,1
#pragma unroll
    for (int c = 0; c < 2; c++) {
        uint32_t sA = smem_u32(smem) + (uint32_t)(c * STAGE_BYTES);
        uint32_t sB = sA + TILE_BYTES;
        load_tile_h(sA, Ablk + c * BKH, K, tid);
        load_tile_h(sB, Wblk + c * BKH, K, tid);
        CP_COMMIT();
    }

    const uint32_t* Asm = (const uint32_t*)smem;

    for (int c = 0; c < nch; c++) {
        int s = c % NSTAGE;
        CP_WAIT(1);
        __syncthreads();

        if (c + 2 < nch) {
            int s2 = (c + 2) % NSTAGE;
            uint32_t sA = smem_u32(smem) + (uint32_t)(s2 * STAGE_BYTES);
            uint32_t sB = sA + TILE_BYTES;
            load_tile_h(sA, Ablk + (c + 2) * BKH, K, tid);
            load_tile_h(sB, Wblk + (c + 2) * BKH, K, tid);
        }
        CP_COMMIT();

        const uint32_t* As = Asm + s * (STAGE_BYTES / 4);
        const uint32_t* Bs = As + (TILE_BYTES / 4);
#pragma unroll
        for (int ks = 0; ks < 4; ks++) {
            int u0 = ((ks * 2)     ^ lr) * 4 + lc;
            int u1 = ((ks * 2 + 1) ^ lr) * 4 + lc;
            uint32_t a[4][4], b[4][2];
#pragma unroll
            for (int mt = 0; mt < 4; mt++) {
                int r = wm * 64 + mt * 16 + lr;
                a[mt][0] = As[r * 32 + u0];
                a[mt][1] = As[(r + 8) * 32 + u0];
                a[mt][2] = As[r * 32 + u1];
                a[mt][3] = As[(r + 8) * 32 + u1];
            }
#pragma unroll
            for (int nt = 0; nt < 4; nt++) {
                int n = wn * 32 + nt * 8 + lr;
                b[nt][0] = Bs[n * 32 + u0];
                b[nt][1] = Bs[n * 32 + u1];
            }
#pragma unroll
            for (int mt = 0; mt < 4; mt++)
#pragma unroll
                for (int nt = 0; nt < 4; nt++)
                    mma_f16(acc[mt][nt], a[mt], b[nt]);
        }
    }

    // ---------------- epilogue (fp16 outputs) ----------------
#pragma unroll
    for (int mt = 0; mt < 4; mt++) {
        int m = bm + wm * 64 + mt * 16 + lr;
        float s0 = 0.f, s1 = 0.f;
#pragma unroll
        for (int nt = 0; nt < 4; nt++) {
            int n = bn + wn * 32 + nt * 8 + lc * 2;
            float2 v0 = make_float2(acc[mt][nt][0], acc[mt][nt][1]);
            float2 v1 = make_float2(acc[mt][nt][2], acc[mt][nt][3]);
            if (epi >= 1) {
                float b0 = bias[n], b1 = bias[n + 1];
                v0.x += b0; v0.y += b1; v1.x += b0; v1.y += b1;
            }
            if (epi == 2) {
                v0.x = gelu_f(v0.x); v0.y = gelu_f(v0.y);
                v1.x = gelu_f(v1.x); v1.y = gelu_f(v1.y);
            }
            if (epi == 1) {
                s0 += v0.x + v0.y;
                s1 += v1.x + v1.y;
            }
            if (epi == 3) {
                float2 r0 = *(const float2*)(res + (size_t)m * N + n);
                float2 r1 = *(const float2*)(res + (size_t)(m + 8) * N + n);
                v0.x += r0.x; v0.y += r0.y; v1.x += r1.x; v1.y += r1.y;
            }
            __half2* Ch = (__half2*)C;
            Ch[((size_t)m * N + n) >> 1] = __floats2half2_rn(v0.x, v0.y);
            Ch[((size_t)(m + 8) * N + n) >> 1] = __floats2half2_rn(v1.x, v1.y);
        }
        if (epi == 1) {
            // rows m..m+7 (lr=0..7) share pooled group m>>3; rows m+8.. share +1
#pragma unroll
            for (int o = 16; o > 0; o >>= 1) {
                s0 += __shfl_xor_sync(0xffffffffu, s0, o);
                s1 += __shfl_xor_sync(0xffffffffu, s1, o);
            }
            if (lane == 0) {
                atomicAdd(&pooled[m >> 3], s0);
                atomicAdd(&pooled[(m >> 3) + 1], s1);
            }
        }
    }
}

// ---------------- fp32 -> fp16 weight conversion ----------------
__global__ __launch_bounds__(256) void f2h_kernel(const float* __restrict__ src,
                                                  __half* __restrict__ dst, int n)
{
    int i = (blockIdx.x * 256 + threadIdx.x) * 4;
    if (i < n) {
        float4 v = *(const float4*)(src + i);
        __half2* d = (__half2*)(dst + i);
        d[0] = __floats2half2_rn(v.x, v.y);
        d[1] = __floats2half2_rn(v.z, v.w);
    }
}

__global__ __launch_bounds__(256) void zero_kernel(float* __restrict__ p, int n)
{
    int i = blockIdx.x * 256 + threadIdx.x;
    if (i < n) p[i] = 0.f;
}

// ---------------- LayerNorm: f32 input -> fp16 output ----------------
__global__ __launch_bounds__(256) void ln_kernel(
    const float* __restrict__ x, const float* __restrict__ w,
    const float* __restrict__ b, __half* __restrict__ out)
{
    int warp = threadIdx.x >> 5, lane = threadIdx.x & 31;
    int row  = blockIdx.x * 8 + warp;
    const float4* xr = (const float4*)(x + (size_t)row * DIM);
    float4 v[4];
    float s = 0.f, ss = 0.f;
#pragma unroll
    for (int i = 0; i < 4; i++) {
        v[i] = xr[lane + 32*i];
        s  += v[i].x + v[i].y + v[i].z + v[i].w;
        ss += v[i].x*v[i].x + v[i].y*v[i].y + v[i].z*v[i].z + v[i].w*v[i].w;
    }
#pragma unroll
    for (int o = 16; o > 0; o >>= 1) {
        s  += __shfl_xor_sync(0xffffffffu, s,  o);
        ss += __shfl_xor_sync(0xffffffffu, ss, o);
    }
    float mean = s * (1.f/DIM);
    float var  = ss * (1.f/DIM) - mean*mean;
    float inv  = rsqrtf(var + LN_EPS);
    __half2* orow = (__half2*)(out + (size_t)row * DIM);
#pragma unroll
    for (int i = 0; i < 4; i++) {
        int c = (lane + 32*i) * 4;
        float rx = (v[i].x - mean) * inv * w[c+0] + b[c+0];
        float ry = (v[i].y - mean) * inv * w[c+1] + b[c+1];
        float rz = (v[i].z - mean) * inv * w[c+2] + b[c+2];
        float rw = (v[i].w - mean) * inv * w[c+3] + b[c+3];
        orow[(c >> 1)]     = __floats2half2_rn(rx, ry);
        orow[(c >> 1) + 1] = __floats2half2_rn(rz, rw);
    }
}

// ---------------- LayerNorm: fp16 input -> fp16 output ----------------
__global__ __launch_bounds__(256) void ln_kernel_h(
    const __half* __restrict__ x, const float* __restrict__ w,
    const float* __restrict__ b, __half* __restrict__ out)
{
    int warp = threadIdx.x >> 5, lane = threadIdx.x & 31;
    int row  = blockIdx.x * 8 + warp;
    const __half2* xr = (const __half2*)(x + (size_t)row * DIM);
    float2 v[8];                            // 8 half2 per lane = 16 values
    float s = 0.f, ss = 0.f;
#pragma unroll
    for (int i = 0; i < 8; i++) {
        v[i] = __half22float2(xr[lane + 32*i]);
        s  += v[i].x + v[i].y;
        ss += v[i].x*v[i].x + v[i].y*v[i].y;
    }
#pragma unroll
    for (int o = 16; o > 0; o >>= 1) {
        s  += __shfl_xor_sync(0xffffffffu, s,  o);
        ss += __shfl_xor_sync(0xffffffffu, ss, o);
    }
    float mean = s * (1.f/DIM);
    float var  = ss * (1.f/DIM) - mean*mean;
    float inv  = rsqrtf(var + LN_EPS);
    __half2* orow = (__half2*)(out + (size_t)row * DIM);
#pragma unroll
    for (int i = 0; i < 8; i++) {
        int c = (lane + 32*i) * 2;
        float rx = (v[i].x - mean) * inv * w[c+0] + b[c+0];
        float ry = (v[i].y - mean) * inv * w[c+1] + b[c+1];
        orow[lane + 32*i] = __floats2half2_rn(rx, ry);
    }
}

// ---------------- XCA pieces (fp16 qkv) ----------------
__global__ __launch_bounds__(256) void kv_cov_kernel(const __half* __restrict__ qkv,
                                                     float* __restrict__ Spart)
{
    int bh = blockIdx.x;
    int split = blockIdx.y;
    int b = bh >> 3, h = bh & 7;
    __shared__ float ks[16][64];
    __shared__ float vs[16][64];
    int tid = threadIdx.x;
    int d = tid & 63, eb = (tid >> 6) * 16;
    float acc[16];
#pragma unroll
    for (int j = 0; j < 16; j++) acc[j] = 0.f;

    int n0 = split * (SEQ / NSPLIT);
    const __half* base = qkv + (size_t)b * SEQ * (3*DIM);
    for (int nc = 0; nc < SEQ/NSPLIT; nc += 16) {
#pragma unroll
        for (int i = 0; i < 2; i++) {
            int l2 = tid + i*256;               // 0..511
            int r = l2 >> 5, c2 = (l2 & 31) * 2;
            const __half* rowp = base + (size_t)(n0 + nc + r) * (3*DIM) + h*64 + c2;
            float2 kf = __half22float2(*(const __half2*)(rowp + DIM));
            float2 vf = __half22float2(*(const __half2*)(rowp + 2*DIM));
            ks[r][c2] = kf.x; ks[r][c2+1] = kf.y;
            vs[r][c2] = vf.x; vs[r][c2+1] = vf.y;
        }
        __syncthreads();
#pragma unroll
        for (int nn = 0; nn < 16; nn++) {
            float kd = ks[nn][d];
#pragma unroll
            for (int j = 0; j < 16; j++) acc[j] += kd * vs[nn][eb + j];
        }
        __syncthreads();
    }
    float* out = Spart + ((size_t)split*64 + bh) * 4096;
#pragma unroll
    for (int j = 0; j < 16; j++) out[d*64 + eb + j] = acc[j];
}

// grid (64 bh, 8 slices of 8 d-rows); arithmetic identical to old version
__global__ __launch_bounds__(256) void softmax_kernel(const float* __restrict__ Spart,
                                                      float* __restrict__ attnT)
{
    int bh = blockIdx.x;
    int r0 = blockIdx.y * 8;
    __shared__ float S[8][65];
    int tid = threadIdx.x;
#pragma unroll
    for (int i = 0; i < 2; i++) {
        int l = tid + i*256;                 // 0..511
        int r = l >> 6, e = l & 63;
        float s = 0.f;
#pragma unroll
        for (int sp = 0; sp < NSPLIT; sp++)
            s += Spart[((size_t)sp*64 + bh) * 4096 + (r0 + r)*64 + e];
        S[r][e] = s * SCALE;
    }
    __syncthreads();
    int warp = tid >> 5, lane = tid & 31;
    float a = S[warp][lane], b = S[warp][lane + 32];
    float mx = fmaxf(a, b);
#pragma unroll
    for (int o = 16; o > 0; o >>= 1) mx = fmaxf(mx, __shfl_xor_sync(0xffffffffu, mx, o));
    float ea = expf(a - mx), eb = expf(b - mx);
    float sum = ea + eb;
#pragma unroll
    for (int o = 16; o > 0; o >>= 1) sum += __shfl_xor_sync(0xffffffffu, sum, o);
    float inv = 1.f / sum;
    int d = r0 + warp;
    attnT[(size_t)bh*4096 + lane*64 + d]        = ea * inv;
    attnT[(size_t)bh*4096 + (lane + 32)*64 + d] = eb * inv;
}

__global__ __launch_bounds__(256) void attn_out_kernel(const __half* __restrict__ qkv,
                                                       const float* __restrict__ attnT,
                                                       __half* __restrict__ out)
{
    int bh = blockIdx.x;
    int b = bh >> 3, h = bh & 7;
    int n0 = blockIdx.y * 64;
    __shared__ float at[64][64];
    __shared__ float qs[64][64];
    int tid = threadIdx.x;
#pragma unroll
    for (int i = 0; i < 16; i++) {
        int l = tid + i*256;
        ((float*)at)[l] = attnT[(size_t)bh*4096 + l];
    }
    // qs: 64 rows x 32 half2 = 2048 half2
#pragma unroll
    for (int i = 0; i < 8; i++) {
        int l2 = tid + i*256;
        int r = l2 >> 5, c2 = (l2 & 31) * 2;
        float2 qf = __half22float2(
            *(const __half2*)(qkv + (size_t)(b*SEQ + n0 + r) * (3*DIM) + h*64 + c2));
        qs[r][c2] = qf.x; qs[r][c2+1] = qf.y;
    }
    __syncthreads();
    int d = tid & 63, nb = (tid >> 6) * 16;
    float acc[16];
#pragma unroll
    for (int j = 0; j < 16; j++) acc[j] = 0.f;
#pragma unroll 8
    for (int e = 0; e < 64; e++) {
        float ad = at[e][d];
#pragma unroll
        for (int j = 0; j < 16; j++) acc[j] += qs[nb + j][e] * ad;
    }
#pragma unroll
    for (int j = 0; j < 16; j++)
        out[(size_t)(b*SEQ + n0 + nb + j) * DIM + h*64 + d] = __float2half_rn(acc[j]);
}

// ---------------- gate / final ----------------
__global__ __launch_bounds__(512) void gate_kernel(const float* __restrict__ pooled,
                                                   const float* __restrict__ w,
                                                   float* __restrict__ gate)
{
    __shared__ float p[514];
    int b = blockIdx.x, c = threadIdx.x;
    p[c + 1] = pooled[b*DIM + c] * (1.f/4096.f);
    if (c == 0) { p[0] = 0.f; p[513] = 0.f; }
    __syncthreads();
    float conv = w[0]*p[c] + w[1]*p[c+1] + w[2]*p[c+2];
    gate[b*DIM + c] = 1.f + 1.f/(1.f + expf(-conv));
}

__global__ __launch_bounds__(256) void final_kernel(const __half* __restrict__ y,
                                                    const __half* __restrict__ x1,
                                                    const float* __restrict__ gate,
                                                    float* __restrict__ out)
{
    __shared__ float sh[32][33];
    int b = blockIdx.z, m0 = blockIdx.x*32, c0 = blockIdx.y*32;
    int tx = threadIdx.x, ty = threadIdx.y;
#pragma unroll
    for (int i = 0; i < 4; i++) {
        int cc = ty + i*8;
        sh[cc][tx] = __half2float(y[(size_t)b*SEQ*DIM + (size_t)(c0+cc)*4096 + m0 + tx])
                   * gate[b*DIM + c0 + cc];
    }
    __syncthreads();
#pragma unroll
    for (int i = 0; i < 4; i++) {
        int mm = ty + i*8;
        size_t o = ((size_t)b*SEQ + m0 + mm) * DIM + c0 + tx;
        out[o] = __half2float(x1[o]) + sh[tx][mm];
    }
}

// ---------------- launch ----------------
extern "C" void kernel_launch(void* const* d_in, const int* in_sizes, int n_in,
                              void* d_out, int out_size)
{
    const float* x      = (const float*)d_in[0];
    const float* ln1_w  = (const float*)d_in[1];
    const float* ln1_b  = (const float*)d_in[2];
    const float* qkv_w  = (const float*)d_in[3];
    const float* proj_w = (const float*)d_in[4];
    const float* proj_b = (const float*)d_in[5];
    const float* ln2_w  = (const float*)d_in[6];
    const float* ln2_b  = (const float*)d_in[7];
    const float* fc1_w  = (const float*)d_in[8];
    const float* fc1_b  = (const float*)d_in[9];
    const float* fc2_w  = (const float*)d_in[10];
    const float* fc2_b  = (const float*)d_in[11];
    const float* eca_w  = (const float*)d_in[12];
    float* out = (float*)d_out;

    __half *curh, *qkvh, *attnouth, *x1h, *hh, *yh, *wqkvh, *wprojh, *wfc1h, *wfc2h;
    float *spart, *attnT, *pooled, *gate;
    cudaGetSymbolAddress((void**)&curh,     g_curh);
    cudaGetSymbolAddress((void**)&qkvh,     g_qkvh);
    cudaGetSymbolAddress((void**)&spart,    g_spart);
    cudaGetSymbolAddress((void**)&attnT,    g_attnT);
    cudaGetSymbolAddress((void**)&attnouth, g_attnouth);
    cudaGetSymbolAddress((void**)&x1h,      g_x1h);
    cudaGetSymbolAddress((void**)&hh,       g_hh);
    cudaGetSymbolAddress((void**)&yh,       g_yh);
    cudaGetSymbolAddress((void**)&pooled,   g_pooled);
    cudaGetSymbolAddress((void**)&gate,     g_gate);
    cudaGetSymbolAddress((void**)&wqkvh,    g_wqkvh);
    cudaGetSymbolAddress((void**)&wprojh,   g_wprojh);
    cudaGetSymbolAddress((void**)&wfc1h,    g_wfc1h);
    cudaGetSymbolAddress((void**)&wfc2h,    g_wfc2h);

    cudaFuncSetAttribute(hgemm, cudaFuncAttributeMaxDynamicSharedMemorySize, GEMM_SMEM);

    // 0. convert weights to fp16; zero pooled accumulator
    f2h_kernel<<<(3*DIM*DIM)/1024, 256>>>(qkv_w, wqkvh, 3*DIM*DIM);
    f2h_kernel<<<(DIM*DIM)/1024, 256>>>(proj_w, wprojh, DIM*DIM);
    f2h_kernel<<<(HIDDEN*DIM)/1024, 256>>>(fc1_w, wfc1h, HIDDEN*DIM);
    f2h_kernel<<<(DIM*HIDDEN)/1024, 256>>>(fc2_w, wfc2h, DIM*HIDDEN);
    zero_kernel<<<(BATCH*DIM)/256, 256>>>(pooled, BATCH*DIM);

    // 1. LN1 -> fp16
    ln_kernel<<<ROWS/8, 256>>>(x, ln1_w, ln1_b, curh);
    // 2. qkv = LN1(x) @ qkv_w^T   (fp16 out)
    hgemm<<<dim3((3*DIM)/BN, ROWS/BM), 256, GEMM_SMEM>>>(curh, wqkvh, qkvh,
                                                         ROWS, 3*DIM, DIM,
                                                         nullptr, nullptr, nullptr, 0);
    // 3-5. cross-covariance attention
    kv_cov_kernel<<<dim3(64, NSPLIT), 256>>>(qkvh, spart);
    softmax_kernel<<<dim3(64, 8), 256>>>(spart, attnT);
    attn_out_kernel<<<dim3(64, SEQ/64), 256>>>(qkvh, attnT, attnouth);
    // 6. x1 = x + attnout @ proj_w^T + proj_b   (fp16 out)
    hgemm<<<dim3(DIM/BN, ROWS/BM), 256, GEMM_SMEM>>>(attnouth, wprojh, x1h,
                                                     ROWS, DIM, DIM,
                                                     proj_b, x, nullptr, 3);
    // 7. LN2 (fp16 in) -> fp16
    ln_kernel_h<<<ROWS/8, 256>>>(x1h, ln2_w, ln2_b, curh);
    // 8. h = gelu(LN2 @ fc1_w^T + fc1_b)  (fp16 out)
    hgemm<<<dim3(HIDDEN/BN, ROWS/BM), 256, GEMM_SMEM>>>(curh, wfc1h, hh,
                                                        ROWS, HIDDEN, DIM,
                                                        fc1_b, nullptr, nullptr, 2);
    // 9. y = h @ fc2_w^T + fc2_b  (fp16 out + fused pooled accumulation)
    hgemm<<<dim3(DIM/BN, ROWS/BM), 256, GEMM_SMEM>>>(hh, wfc2h, yh,
                                                     ROWS, DIM, HIDDEN,
                                                     fc2_b, nullptr, pooled, 1);
    // 10-11. ECA gate + transposed gather epilogue
    gate_kernel<<<BATCH, DIM>>>(pooled, eca_w, gate);
    final_kernel<<<dim3(SEQ/32, DIM/32, BATCH), dim3(32, 8)>>>(yh, x1h, gate, out);
}

// round 14
// speedup vs baseline: 1.5374x; 1.5374x over previous
#include <cuda_runtime.h>
#include <cuda_fp16.h>
#include <math.h>
#include <stdint.h>

// ---------------- problem constants ----------------
#define BATCH 8
#define SEQ   4096
#define DIM   512
#define HIDDEN 2048
#define ROWS  (BATCH*SEQ)           // 32768
#define SCALE 0.125f
#define LN_EPS 1e-5f
#define NSPLIT 8

// ---------------- scratch ----------------
__device__ __half g_curh[ROWS*DIM];
__device__ __half g_qkvh[ROWS*3*DIM];
__device__ float  g_spart[NSPLIT*64*64*64];
__device__ float  g_attnT[64*64*64];
__device__ __half g_attnouth[ROWS*DIM];
__device__ __half g_x1h[ROWS*DIM];
__device__ __half g_hh[ROWS*HIDDEN];
__device__ __half g_yh[ROWS*DIM];
__device__ float  g_pooled[BATCH*DIM];
__device__ float  g_gate[BATCH*DIM];
__device__ __half g_wqkvh[3*DIM*DIM];
__device__ __half g_wprojh[DIM*DIM];
__device__ __half g_wfc1h[HIDDEN*DIM];
__device__ __half g_wfc2h[DIM*HIDDEN];

// ================= helpers =================
__device__ __forceinline__ uint32_t smem_u32(const void* p) {
    uint32_t a;
    asm("{ .reg .u64 t; cvta.to.shared.u64 t, %1; cvt.u32.u64 %0, t; }" : "=r"(a) : "l"(p));
    return a;
}
__device__ __forceinline__ void cp_async16(uint32_t dst, const void* src) {
    asm volatile("cp.async.cg.shared.global [%0], [%1], 16;" :: "r"(dst), "l"(src) : "memory");
}
#define CP_COMMIT() asm volatile("cp.async.commit_group;" ::: "memory")
#define CP_WAIT(n)  asm volatile("cp.async.wait_group %0;" :: "n"(n) : "memory")

__device__ __forceinline__ void mma_f16(float* c, const uint32_t* a, const uint32_t* b) {
    asm volatile(
        "mma.sync.aligned.m16n8k16.row.col.f32.f16.f16.f32 "
        "{%0,%1,%2,%3}, {%4,%5,%6,%7}, {%8,%9}, {%0,%1,%2,%3};"
        : "+f"(c[0]), "+f"(c[1]), "+f"(c[2]), "+f"(c[3])
        : "r"(a[0]), "r"(a[1]), "r"(a[2]), "r"(a[3]), "r"(b[0]), "r"(b[1]));
}
__device__ __forceinline__ float gelu_f(float v) {
    return 0.5f * v * (1.f + erff(v * 0.70710678118f));
}

// ================= FP16 mma.sync GEMM =================
// C[m,n] = sum_k A[m,k] * W[n,k]   (+epilogue)
// epi: 0 = fp16 out, no bias                (qkv)
//      1 = fp16 out, +bias, pooled atomics  (fc2)
//      2 = fp16 out, +bias+gelu             (fc1)
//      3 = fp16 out, +bias+res(f32)         (proj)
#define BM 128
#define BN 128
#define BKH 64                                  // halfs per chunk: 128B rows
#define NSTAGE 3
#define TILE_BYTES (BM*BKH*2)                   // 16KB
#define STAGE_BYTES (2*TILE_BYTES)              // 32KB (A+B)
#define GEMM_SMEM (NSTAGE*STAGE_BYTES)          // 96KB

__device__ __forceinline__ void load_tile_h(uint32_t dst, const __half* __restrict__ src,
                                            int K, int tid)
{
    int row = tid >> 3;       // 0..31
    int u   = tid & 7;        // 16B unit within 128B row
#pragma unroll
    for (int i = 0; i < 4; i++) {
        int r = row + i * 32;
        uint32_t soff = (uint32_t)(r * 8 + (u ^ (r & 7))) * 16;
        cp_async16(dst + soff, src + (size_t)r * K + u * 8);
    }
}

__global__ void __launch_bounds__(256, 2)
hgemm(const __half* __restrict__ A, const __half* __restrict__ W,
      void* __restrict__ Cv, int M, int N, int K,
      const float* __restrict__ bias, const float* __restrict__ res,
      float* __restrict__ pooled, int epi)
{
    extern __shared__ __align__(16) char smem[];
    const int tid  = threadIdx.x;
    const int warp = tid >> 5, lane = tid & 31;
    const int lr = lane >> 2, lc = lane & 3;
    const int wm = warp & 1, wn = warp >> 1;      // 2 x 4 warp grid
    const int bm = blockIdx.y * BM, bn = blockIdx.x * BN;
    const int nch = K / BKH;

    const __half* Ablk = A + (size_t)bm * K;
    const __half* Wblk = W + (size_t)bn * K;

    float acc[4][4][4];
#pragma unroll
    for (int i = 0; i < 4; i++)
#pragma unroll
        for (int j = 0; j < 4; j++)
#pragma unroll
            for (int q = 0; q < 4; q++) acc[i][j][q] = 0.f;

    // prologue: stages 0,1
#pragma unroll
    for (int c = 0; c < 2; c++) {
        uint32_t sA = smem_u32(smem) + (uint32_t)(c * STAGE_BYTES);
        uint32_t sB = sA + TILE_BYTES;
        load_tile_h(sA, Ablk + c * BKH, K, tid);
        load_tile_h(sB, Wblk + c * BKH, K, tid);
        CP_COMMIT();
    }

    const uint32_t* Asm = (const uint32_t*)smem;

    for (int c = 0; c < nch; c++) {
        int s = c % NSTAGE;
        CP_WAIT(1);
        __syncthreads();

        if (c + 2 < nch) {
            int s2 = (c + 2) % NSTAGE;
            uint32_t sA = smem_u32(smem) + (uint32_t)(s2 * STAGE_BYTES);
            uint32_t sB = sA + TILE_BYTES;
            load_tile_h(sA, Ablk + (c + 2) * BKH, K, tid);
            load_tile_h(sB, Wblk + (c + 2) * BKH, K, tid);
        }
        CP_COMMIT();

        const uint32_t* As = Asm + s * (STAGE_BYTES / 4);
        const uint32_t* Bs = As + (TILE_BYTES / 4);
#pragma unroll
        for (int ks = 0; ks < 4; ks++) {
            int u0 = ((ks * 2)     ^ lr) * 4 + lc;
            int u1 = ((ks * 2 + 1) ^ lr) * 4 + lc;
            uint32_t a[4][4], b[4][2];
#pragma unroll
            for (int mt = 0; mt < 4; mt++) {
                int r = wm * 64 + mt * 16 + lr;
                a[mt][0] = As[r * 32 + u0];
                a[mt][1] = As[(r + 8) * 32 + u0];
                a[mt][2] = As[r * 32 + u1];
                a[mt][3] = As[(r + 8) * 32 + u1];
            }
#pragma unroll
            for (int nt = 0; nt < 4; nt++) {
                int n = wn * 32 + nt * 8 + lr;
                b[nt][0] = Bs[n * 32 + u0];
                b[nt][1] = Bs[n * 32 + u1];
            }
#pragma unroll
            for (int mt = 0; mt < 4; mt++)
#pragma unroll
                for (int nt = 0; nt < 4; nt++)
                    mma_f16(acc[mt][nt], a[mt], b[nt]);
        }
    }

    // ---------------- epilogue ----------------
#pragma unroll
    for (int mt = 0; mt < 4; mt++) {
        int m = bm + wm * 64 + mt * 16 + lr;
        float s0 = 0.f, s1 = 0.f;
#pragma unroll
        for (int nt = 0; nt < 4; nt++) {
            int n = bn + wn * 32 + nt * 8 + lc * 2;
            float2 v0 = make_float2(acc[mt][nt][0], acc[mt][nt][1]);
            float2 v1 = make_float2(acc[mt][nt][2], acc[mt][nt][3]);
            if (epi >= 1) {
                float b0 = bias[n], b1 = bias[n + 1];
                v0.x += b0; v0.y += b1; v1.x += b0; v1.y += b1;
            }
            if (epi == 2) {
                v0.x = gelu_f(v0.x); v0.y = gelu_f(v0.y);
                v1.x = gelu_f(v1.x); v1.y = gelu_f(v1.y);
            }
            if (epi == 1) {
                s0 += v0.x + v0.y;
                s1 += v1.x + v1.y;
            }
            if (epi == 3) {
                __half2* Ch = (__half2*)Cv;
                float2 r0 = *(const float2*)(res + (size_t)m * N + n);
                float2 r1 = *(const float2*)(res + (size_t)(m + 8) * N + n);
                v0.x += r0.x; v0.y += r0.y; v1.x += r1.x; v1.y += r1.y;
                Ch[((size_t)m * N + n) >> 1] = __floats2half2_rn(v0.x, v0.y);
                Ch[((size_t)(m + 8) * N + n) >> 1] = __floats2half2_rn(v1.x, v1.y);
            } else {
                __half2* Ch = (__half2*)Cv;
                Ch[((size_t)m * N + n) >> 1] = __floats2half2_rn(v0.x, v0.y);
                Ch[((size_t)(m + 8) * N + n) >> 1] = __floats2half2_rn(v1.x, v1.y);
            }
        }
        if (epi == 1) {
            // rows m..m+7 (lr=0..7) share pooled group m>>3; rows m+8.. share +1
#pragma unroll
            for (int o = 16; o > 0; o >>= 1) {
                s0 += __shfl_xor_sync(0xffffffffu, s0, o);
                s1 += __shfl_xor_sync(0xffffffffu, s1, o);
            }
            if (lane == 0) {
                atomicAdd(&pooled[m >> 3], s0);
                atomicAdd(&pooled[(m >> 3) + 1], s1);
            }
        }
    }
}

// ---------------- fp32 -> fp16 weight conversion ----------------
__global__ __launch_bounds__(256) void f2h_kernel(const float* __restrict__ src,
                                                  __half* __restrict__ dst, int n)
{
    int i = (blockIdx.x * 256 + threadIdx.x) * 4;
    if (i < n) {
        float4 v = *(const float4*)(src + i);
        __half2* d = (__half2*)(dst + i);
        d[0] = __floats2half2_rn(v.x, v.y);
        d[1] = __floats2half2_rn(v.z, v.w);
    }
}

__global__ __launch_bounds__(256) void zero_kernel(float* __restrict__ p, int n)
{
    int i = blockIdx.x * 256 + threadIdx.x;
    if (i < n) p[i] = 0.f;
}

// ---------------- LayerNorm: f32 input -> fp16 output ----------------
__global__ __launch_bounds__(256) void ln_kernel(
    const float* __restrict__ x, const float* __restrict__ w,
    const float* __restrict__ b, __half* __restrict__ out)
{
    int warp = threadIdx.x >> 5, lane = threadIdx.x & 31;
    int row  = blockIdx.x * 8 + warp;
    const float4* xr = (const float4*)(x + (size_t)row * DIM);
    float4 v[4];
    float s = 0.f, ss = 0.f;
#pragma unroll
    for (int i = 0; i < 4; i++) {
        v[i] = xr[lane + 32*i];
        s  += v[i].x + v[i].y + v[i].z + v[i].w;
        ss += v[i].x*v[i].x + v[i].y*v[i].y + v[i].z*v[i].z + v[i].w*v[i].w;
    }
#pragma unroll
    for (int o = 16; o > 0; o >>= 1) {
        s  += __shfl_xor_sync(0xffffffffu, s,  o);
        ss += __shfl_xor_sync(0xffffffffu, ss, o);
    }
    float mean = s * (1.f/DIM);
    float var  = ss * (1.f/DIM) - mean*mean;
    float inv  = rsqrtf(var + LN_EPS);
    __half2* orow = (__half2*)(out + (size_t)row * DIM);
#pragma unroll
    for (int i = 0; i < 4; i++) {
        int c = (lane + 32*i) * 4;
        float rx = (v[i].x - mean) * inv * w[c+0] + b[c+0];
        float ry = (v[i].y - mean) * inv * w[c+1] + b[c+1];
        float rz = (v[i].z - mean) * inv * w[c+2] + b[c+2];
        float rw = (v[i].w - mean) * inv * w[c+3] + b[c+3];
        orow[(c >> 1)]     = __floats2half2_rn(rx, ry);
        orow[(c >> 1) + 1] = __floats2half2_rn(rz, rw);
    }
}

// ---------------- LayerNorm: fp16 input -> fp16 output ----------------
__global__ __launch_bounds__(256) void ln_kernel_h(
    const __half* __restrict__ x, const float* __restrict__ w,
    const float* __restrict__ b, __half* __restrict__ out)
{
    int warp = threadIdx.x >> 5, lane = threadIdx.x & 31;
    int row  = blockIdx.x * 8 + warp;
    const __half2* xr = (const __half2*)(x + (size_t)row * DIM);
    float2 v[8];                            // 8 half2 per lane = 16 values
    float s = 0.f, ss = 0.f;
#pragma unroll
    for (int i = 0; i < 8; i++) {
        v[i] = __half22float2(xr[lane + 32*i]);
        s  += v[i].x + v[i].y;
        ss += v[i].x*v[i].x + v[i].y*v[i].y;
    }
#pragma unroll
    for (int o = 16; o > 0; o >>= 1) {
        s  += __shfl_xor_sync(0xffffffffu, s,  o);
        ss += __shfl_xor_sync(0xffffffffu, ss, o);
    }
    float mean = s * (1.f/DIM);
    float var  = ss * (1.f/DIM) - mean*mean;
    float inv  = rsqrtf(var + LN_EPS);
    __half2* orow = (__half2*)(out + (size_t)row * DIM);
#pragma unroll
    for (int i = 0; i < 8; i++) {
        int c = (lane + 32*i) * 2;
        float rx = (v[i].x - mean) * inv * w[c+0] + b[c+0];
        float ry = (v[i].y - mean) * inv * w[c+1] + b[c+1];
        orow[lane + 32*i] = __floats2half2_rn(rx, ry);
    }
}

// ---------------- XCA pieces (fp16 qkv) ----------------
__global__ __launch_bounds__(256) void kv_cov_kernel(const __half* __restrict__ qkv,
                                                     float* __restrict__ Spart)
{
    int bh = blockIdx.x;
    int split = blockIdx.y;
    int b = bh >> 3, h = bh & 7;
    __shared__ float ks[16][64];
    __shared__ float vs[16][64];
    int tid = threadIdx.x;
    int d = tid & 63, eb = (tid >> 6) * 16;
    float acc[16];
#pragma unroll
    for (int j = 0; j < 16; j++) acc[j] = 0.f;

    int n0 = split * (SEQ / NSPLIT);
    const __half* base = qkv + (size_t)b * SEQ * (3*DIM);
    for (int nc = 0; nc < SEQ/NSPLIT; nc += 16) {
        // 16 rows x 32 half2 = 512 half2
#pragma unroll
        for (int i = 0; i < 2; i++) {
            int l2 = tid + i*256;               // 0..511
            int r = l2 >> 5, c2 = (l2 & 31) * 2;
            const __half* rowp = base + (size_t)(n0 + nc + r) * (3*DIM) + h*64 + c2;
            float2 kf = __half22float2(*(const __half2*)(rowp + DIM));
            float2 vf = __half22float2(*(const __half2*)(rowp + 2*DIM));
            ks[r][c2] = kf.x; ks[r][c2+1] = kf.y;
            vs[r][c2] = vf.x; vs[r][c2+1] = vf.y;
        }
        __syncthreads();
#pragma unroll
        for (int nn = 0; nn < 16; nn++) {
            float kd = ks[nn][d];
#pragma unroll
            for (int j = 0; j < 16; j++) acc[j] += kd * vs[nn][eb + j];
        }
        __syncthreads();
    }
    float* out = Spart + ((size_t)split*64 + bh) * 4096;
#pragma unroll
    for (int j = 0; j < 16; j++) out[d*64 + eb + j] = acc[j];
}

__global__ __launch_bounds__(256) void softmax_kernel(const float* __restrict__ Spart,
                                                      float* __restrict__ attnT)
{
    int bh = blockIdx.x;
    __shared__ float S[64][65];
    int tid = threadIdx.x;
#pragma unroll
    for (int i = 0; i < 16; i++) {
        int l = tid + i*256;
        float s = 0.f;
#pragma unroll
        for (int sp = 0; sp < NSPLIT; sp++)
            s += Spart[((size_t)sp*64 + bh) * 4096 + l];
        S[l >> 6][l & 63] = s * SCALE;
    }
    __syncthreads();
    int warp = tid >> 5, lane = tid & 31;
    for (int r = warp; r < 64; r += 8) {
        float a = S[r][lane], b = S[r][lane + 32];
        float mx = fmaxf(a, b);
#pragma unroll
        for (int o = 16; o > 0; o >>= 1) mx = fmaxf(mx, __shfl_xor_sync(0xffffffffu, mx, o));
        float ea = expf(a - mx), eb = expf(b - mx);
        float sum = ea + eb;
#pragma unroll
        for (int o = 16; o > 0; o >>= 1) sum += __shfl_xor_sync(0xffffffffu, sum, o);
        float inv = 1.f / sum;
        S[r][lane] = ea * inv;
        S[r][lane + 32] = eb * inv;
    }
    __syncthreads();
#pragma unroll
    for (int i = 0; i < 16; i++) {
        int l = tid + i*256;
        attnT[(size_t)bh*4096 + l] = S[l & 63][l >> 6];
    }
}

__global__ __launch_bounds__(256) void attn_out_kernel(const __half* __restrict__ qkv,
                                                       const float* __restrict__ attnT,
                                                       __half* __restrict__ out)
{
    int bh = blockIdx.x;
    int b = bh >> 3, h = bh & 7;
    int n0 = blockIdx.y * 64;
    __shared__ float at[64][64];
    __shared__ float qs[64][64];
    int tid = threadIdx.x;
#pragma unroll
    for (int i = 0; i < 16; i++) {
        int l = tid + i*256;
        ((float*)at)[l] = attnT[(size_t)bh*4096 + l];
    }
    // qs: 64 rows x 32 half2 = 2048 half2 -> 8 iterations of 256 threads
#pragma unroll
    for (int i = 0; i < 8; i++) {
        int l2 = tid + i*256;                    // 0..2047
        int r = l2 >> 5, c2 = (l2 & 31) * 2;
        float2 qf = __half22float2(
            *(const __half2*)(qkv + (size_t)(b*SEQ + n0 + r) * (3*DIM) + h*64 + c2));
        qs[r][c2] = qf.x; qs[r][c2+1] = qf.y;
    }
    __syncthreads();
    int d = tid & 63, nb = (tid >> 6) * 16;
    float acc[16];
#pragma unroll
    for (int j = 0; j < 16; j++) acc[j] = 0.f;
#pragma unroll 8
    for (int e = 0; e < 64; e++) {
        float ad = at[e][d];
#pragma unroll
        for (int j = 0; j < 16; j++) acc[j] += qs[nb + j][e] * ad;
    }
#pragma unroll
    for (int j = 0; j < 16; j++)
        out[(size_t)(b*SEQ + n0 + nb + j) * DIM + h*64 + d] = __float2half_rn(acc[j]);
}

// ---------------- gate / final ----------------
__global__ __launch_bounds__(512) void gate_kernel(const float* __restrict__ pooled,
                                                   const float* __restrict__ w,
                                                   float* __restrict__ gate)
{
    __shared__ float p[514];
    int b = blockIdx.x, c = threadIdx.x;
    p[c + 1] = pooled[b*DIM + c] * (1.f/4096.f);
    if (c == 0) { p[0] = 0.f; p[513] = 0.f; }
    __syncthreads();
    float conv = w[0]*p[c] + w[1]*p[c+1] + w[2]*p[c+2];
    gate[b*DIM + c] = 1.f + 1.f/(1.f + expf(-conv));
}

__global__ __launch_bounds__(256) void final_kernel(const __half* __restrict__ y,
                                                    const __half* __restrict__ x1,
                                                    const float* __restrict__ gate,
                                                    float* __restrict__ out)
{
    __shared__ float sh[32][33];
    int b = blockIdx.z, m0 = blockIdx.x*32, c0 = blockIdx.y*32;
    int tx = threadIdx.x, ty = threadIdx.y;
#pragma unroll
    for (int i = 0; i < 4; i++) {
        int cc = ty + i*8;
        sh[cc][tx] = __half2float(y[(size_t)b*SEQ*DIM + (size_t)(c0+cc)*4096 + m0 + tx])
                   * gate[b*DIM + c0 + cc];
    }
    __syncthreads();
#pragma unroll
    for (int i = 0; i < 4; i++) {
        int mm = ty + i*8;
        size_t o = ((size_t)b*SEQ + m0 + mm) * DIM + c0 + tx;
        out[o] = __half2float(x1[o]) + sh[tx][mm];
    }
}

// ---------------- launch ----------------
extern "C" void kernel_launch(void* const* d_in, const int* in_sizes, int n_in,
                              void* d_out, int out_size)
{
    const float* x      = (const float*)d_in[0];
    const float* ln1_w  = (const float*)d_in[1];
    const float* ln1_b  = (const float*)d_in[2];
    const float* qkv_w  = (const float*)d_in[3];
    const float* proj_w = (const float*)d_in[4];
    const float* proj_b = (const float*)d_in[5];
    const float* ln2_w  = (const float*)d_in[6];
    const float* ln2_b  = (const float*)d_in[7];
    const float* fc1_w  = (const float*)d_in[8];
    const float* fc1_b  = (const float*)d_in[9];
    const float* fc2_w  = (const float*)d_in[10];
    const float* fc2_b  = (const float*)d_in[11];
    const float* eca_w  = (const float*)d_in[12];
    float* out = (float*)d_out;

    __half *curh, *qkvh, *attnouth, *x1h, *hh, *yh, *wqkvh, *wprojh, *wfc1h, *wfc2h;
    float *spart, *attnT, *pooled, *gate;
    cudaGetSymbolAddress((void**)&curh,     g_curh);
    cudaGetSymbolAddress((void**)&qkvh,     g_qkvh);
    cudaGetSymbolAddress((void**)&spart,    g_spart);
    cudaGetSymbolAddress((void**)&attnT,    g_attnT);
    cudaGetSymbolAddress((void**)&attnouth, g_attnouth);
    cudaGetSymbolAddress((void**)&x1h,      g_x1h);
    cudaGetSymbolAddress((void**)&hh,       g_hh);
    cudaGetSymbolAddress((void**)&yh,       g_yh);
    cudaGetSymbolAddress((void**)&pooled,   g_pooled);
    cudaGetSymbolAddress((void**)&gate,     g_gate);
    cudaGetSymbolAddress((void**)&wqkvh,    g_wqkvh);
    cudaGetSymbolAddress((void**)&wprojh,   g_wprojh);
    cudaGetSymbolAddress((void**)&wfc1h,    g_wfc1h);
    cudaGetSymbolAddress((void**)&wfc2h,    g_wfc2h);

    cudaFuncSetAttribute(hgemm, cudaFuncAttributeMaxDynamicSharedMemorySize, GEMM_SMEM);

    // 0. convert weights to fp16; zero pooled accumulator
    f2h_kernel<<<(3*DIM*DIM)/1024, 256>>>(qkv_w, wqkvh, 3*DIM*DIM);
    f2h_kernel<<<(DIM*DIM)/1024, 256>>>(proj_w, wprojh, DIM*DIM);
    f2h_kernel<<<(HIDDEN*DIM)/1024, 256>>>(fc1_w, wfc1h, HIDDEN*DIM);
    f2h_kernel<<<(DIM*HIDDEN)/1024, 256>>>(fc2_w, wfc2h, DIM*HIDDEN);
    zero_kernel<<<(BATCH*DIM)/256, 256>>>(pooled, BATCH*DIM);

    // 1. LN1 -> fp16
    ln_kernel<<<ROWS/8, 256>>>(x, ln1_w, ln1_b, curh);
    // 2. qkv = LN1(x) @ qkv_w^T   (fp16 out)
    hgemm<<<dim3((3*DIM)/BN, ROWS/BM), 256, GEMM_SMEM>>>(curh, wqkvh, qkvh,
                                                         ROWS, 3*DIM, DIM,
                                                         nullptr, nullptr, nullptr, 0);
    // 3-5. cross-covariance attention
    kv_cov_kernel<<<dim3(64, NSPLIT), 256>>>(qkvh, spart);
    softmax_kernel<<<64, 256>>>(spart, attnT);
    attn_out_kernel<<<dim3(64, SEQ/64), 256>>>(qkvh, attnT, attnouth);
    // 6. x1 = x + attnout @ proj_w^T + proj_b   (fp16 out)
    hgemm<<<dim3(DIM/BN, ROWS/BM), 256, GEMM_SMEM>>>(attnouth, wprojh, x1h,
                                                     ROWS, DIM, DIM,
                                                     proj_b, x, nullptr, 3);
    // 7. LN2 (fp16 in) -> fp16
    ln_kernel_h<<<ROWS/8, 256>>>(x1h, ln2_w, ln2_b, curh);
    // 8. h = gelu(LN2 @ fc1_w^T + fc1_b)  (fp16 out)
    hgemm<<<dim3(HIDDEN/BN, ROWS/BM), 256, GEMM_SMEM>>>(curh, wfc1h, hh,
                                                        ROWS, HIDDEN, DIM,
                                                        fc1_b, nullptr, nullptr, 2);
    // 9. y = h @ fc2_w^T + fc2_b  (fp16 out + fused pooled accumulation)
    hgemm<<<dim3(DIM/BN, ROWS/BM), 256, GEMM_SMEM>>>(hh, wfc2h, yh,
                                                     ROWS, DIM, HIDDEN,
                                                     fc2_b, nullptr, pooled, 1);
    // 10-11. ECA gate + transposed gather epilogue
    gate_kernel<<<BATCH, DIM>>>(pooled, eca_w, gate);
    final_kernel<<<dim3(SEQ/32, DIM/32, BATCH), dim3(32, 8)>>>(yh, x1h, gate, out);
}

// round 16
// speedup vs baseline: 1.5404x; 1.0019x over previous
#include <cuda_runtime.h>
#include <cuda_fp16.h>
#include <math.h>
#include <stdint.h>

// ---------------- problem constants ----------------
#define BATCH 8
#define SEQ   4096
#define DIM   512
#define HIDDEN 2048
#define ROWS  (BATCH*SEQ)           // 32768
#define SCALE 0.125f
#define LN_EPS 1e-5f
#define NSPLIT 8

// ---------------- scratch ----------------
__device__ __half g_curh[ROWS*DIM];
__device__ __half g_qkvh[ROWS*3*DIM];
__device__ float  g_spart[NSPLIT*64*64*64];
__device__ float  g_attnT[64*64*64];
__device__ __half g_attnouth[ROWS*DIM];
__device__ __half g_x1h[ROWS*DIM];
__device__ __half g_hh[ROWS*HIDDEN];
__device__ __half g_yh[ROWS*DIM];
__device__ float  g_pooled[BATCH*DIM];
__device__ __half g_wqkvh[3*DIM*DIM];
__device__ __half g_wprojh[DIM*DIM];
__device__ __half g_wfc1h[HIDDEN*DIM];
__device__ __half g_wfc2h[DIM*HIDDEN];

// ================= helpers =================
__device__ __forceinline__ uint32_t smem_u32(const void* p) {
    uint32_t a;
    asm("{ .reg .u64 t; cvta.to.shared.u64 t, %1; cvt.u32.u64 %0, t; }" : "=r"(a) : "l"(p));
    return a;
}
__device__ __forceinline__ void cp_async16(uint32_t dst, const void* src) {
    asm volatile("cp.async.cg.shared.global [%0], [%1], 16;" :: "r"(dst), "l"(src) : "memory");
}
#define CP_COMMIT() asm volatile("cp.async.commit_group;" ::: "memory")
#define CP_WAIT(n)  asm volatile("cp.async.wait_group %0;" :: "n"(n) : "memory")

__device__ __forceinline__ void mma_f16(float* c, const uint32_t* a, const uint32_t* b) {
    asm volatile(
        "mma.sync.aligned.m16n8k16.row.col.f32.f16.f16.f32 "
        "{%0,%1,%2,%3}, {%4,%5,%6,%7}, {%8,%9}, {%0,%1,%2,%3};"
        : "+f"(c[0]), "+f"(c[1]), "+f"(c[2]), "+f"(c[3])
        : "r"(a[0]), "r"(a[1]), "r"(a[2]), "r"(a[3]), "r"(b[0]), "r"(b[1]));
}
__device__ __forceinline__ float gelu_f(float v) {
    return 0.5f * v * (1.f + erff(v * 0.70710678118f));
}

// ================= FP16 mma.sync GEMM =================
// C[m,n] = sum_k A[m,k] * W[n,k]   (+epilogue)
// epi: 0 = fp16 out, no bias                (qkv)
//      1 = fp16 out, +bias, pooled atomics  (fc2)
//      2 = fp16 out, +bias+gelu             (fc1)
//      3 = fp16 out, +bias+res(f32)         (proj)
#define BM 128
#define BN 128
#define BKH 64                                  // halfs per chunk: 128B rows
#define NSTAGE 3
#define TILE_BYTES (BM*BKH*2)                   // 16KB
#define STAGE_BYTES (2*TILE_BYTES)              // 32KB (A+B)
#define GEMM_SMEM (NSTAGE*STAGE_BYTES)          // 96KB

__device__ __forceinline__ void load_tile_h(uint32_t dst, const __half* __restrict__ src,
                                            int K, int tid)
{
    int row = tid >> 3;       // 0..31
    int u   = tid & 7;        // 16B unit within 128B row
#pragma unroll
    for (int i = 0; i < 4; i++) {
        int r = row + i * 32;
        uint32_t soff = (uint32_t)(r * 8 + (u ^ (r & 7))) * 16;
        cp_async16(dst + soff, src + (size_t)r * K + u * 8);
    }
}

__global__ void __launch_bounds__(256, 2)
hgemm(const __half* __restrict__ A, const __half* __restrict__ W,
      void* __restrict__ Cv, int M, int N, int K,
      const float* __restrict__ bias, const float* __restrict__ res,
      float* __restrict__ pooled, int epi)
{
    extern __shared__ __align__(16) char smem[];
    const int tid  = threadIdx.x;
    const int warp = tid >> 5, lane = tid & 31;
    const int lr = lane >> 2, lc = lane & 3;
    const int wm = warp & 1, wn = warp >> 1;      // 2 x 4 warp grid
    const int bm = blockIdx.y * BM, bn = blockIdx.x * BN;
    const int nch = K / BKH;

    const __half* Ablk = A + (size_t)bm * K;
    const __half* Wblk = W + (size_t)bn * K;

    float acc[4][4][4];
#pragma unroll
    for (int i = 0; i < 4; i++)
#pragma unroll
        for (int j = 0; j < 4; j++)
#pragma unroll
            for (int q = 0; q < 4; q++) acc[i][j][q] = 0.f;

    // prologue: stages 0,1
#pragma unroll
    for (int c = 0; c < 2; c++) {
        uint32_t sA = smem_u32(smem) + (uint32_t)(c * STAGE_BYTES);
        uint32_t sB = sA + TILE_BYTES;
        load_tile_h(sA, Ablk + c * BKH, K, tid);
        load_tile_h(sB, Wblk + c * BKH, K, tid);
        CP_COMMIT();
    }

    const uint32_t* Asm = (const uint32_t*)smem;

    for (int c = 0; c < nch; c++) {
        int s = c % NSTAGE;
        CP_WAIT(1);
        __syncthreads();

        if (c + 2 < nch) {
            int s2 = (c + 2) % NSTAGE;
            uint32_t sA = smem_u32(smem) + (uint32_t)(s2 * STAGE_BYTES);
            uint32_t sB = sA + TILE_BYTES;
            load_tile_h(sA, Ablk + (c + 2) * BKH, K, tid);
            load_tile_h(sB, Wblk + (c + 2) * BKH, K, tid);
        }
        CP_COMMIT();

        const uint32_t* As = Asm + s * (STAGE_BYTES / 4);
        const uint32_t* Bs = As + (TILE_BYTES / 4);
#pragma unroll
        for (int ks = 0; ks < 4; ks++) {
            int u0 = ((ks * 2)     ^ lr) * 4 + lc;
            int u1 = ((ks * 2 + 1) ^ lr) * 4 + lc;
            uint32_t a[4][4], b[4][2];
#pragma unroll
            for (int mt = 0; mt < 4; mt++) {
                int r = wm * 64 + mt * 16 + lr;
                a[mt][0] = As[r * 32 + u0];
                a[mt][1] = As[(r + 8) * 32 + u0];
                a[mt][2] = As[r * 32 + u1];
                a[mt][3] = As[(r + 8) * 32 + u1];
            }
#pragma unroll
            for (int nt = 0; nt < 4; nt++) {
                int n = wn * 32 + nt * 8 + lr;
                b[nt][0] = Bs[n * 32 + u0];
                b[nt][1] = Bs[n * 32 + u1];
            }
#pragma unroll
            for (int mt = 0; mt < 4; mt++)
#pragma unroll
                for (int nt = 0; nt < 4; nt++)
                    mma_f16(acc[mt][nt], a[mt], b[nt]);
        }
    }

    // ---------------- epilogue ----------------
#pragma unroll
    for (int mt = 0; mt < 4; mt++) {
        int m = bm + wm * 64 + mt * 16 + lr;
        float s0 = 0.f, s1 = 0.f;
#pragma unroll
        for (int nt = 0; nt < 4; nt++) {
            int n = bn + wn * 32 + nt * 8 + lc * 2;
            float2 v0 = make_float2(acc[mt][nt][0], acc[mt][nt][1]);
            float2 v1 = make_float2(acc[mt][nt][2], acc[mt][nt][3]);
            if (epi >= 1) {
                float b0 = bias[n], b1 = bias[n + 1];
                v0.x += b0; v0.y += b1; v1.x += b0; v1.y += b1;
            }
            if (epi == 2) {
                v0.x = gelu_f(v0.x); v0.y = gelu_f(v0.y);
                v1.x = gelu_f(v1.x); v1.y = gelu_f(v1.y);
            }
            if (epi == 1) {
                s0 += v0.x + v0.y;
                s1 += v1.x + v1.y;
            }
            if (epi == 3) {
                __half2* Ch = (__half2*)Cv;
                float2 r0 = *(const float2*)(res + (size_t)m * N + n);
                float2 r1 = *(const float2*)(res + (size_t)(m + 8) * N + n);
                v0.x += r0.x; v0.y += r0.y; v1.x += r1.x; v1.y += r1.y;
                Ch[((size_t)m * N + n) >> 1] = __floats2half2_rn(v0.x, v0.y);
                Ch[((size_t)(m + 8) * N + n) >> 1] = __floats2half2_rn(v1.x, v1.y);
            } else {
                __half2* Ch = (__half2*)Cv;
                Ch[((size_t)m * N + n) >> 1] = __floats2half2_rn(v0.x, v0.y);
                Ch[((size_t)(m + 8) * N + n) >> 1] = __floats2half2_rn(v1.x, v1.y);
            }
        }
        if (epi == 1) {
            // rows m..m+7 (lr=0..7) share pooled group m>>3; rows m+8.. share +1
#pragma unroll
            for (int o = 16; o > 0; o >>= 1) {
                s0 += __shfl_xor_sync(0xffffffffu, s0, o);
                s1 += __shfl_xor_sync(0xffffffffu, s1, o);
            }
            if (lane == 0) {
                atomicAdd(&pooled[m >> 3], s0);
                atomicAdd(&pooled[(m >> 3) + 1], s1);
            }
        }
    }
}

// ---------------- consolidated setup: 4x weight f32->f16 + pooled zero ----------------
#define NQKV (3*DIM*DIM)
#define NPROJ (DIM*DIM)
#define NFC1 (HIDDEN*DIM)
#define NFC2 (DIM*HIDDEN)
#define NTOT4 ((NQKV+NPROJ+NFC1+NFC2)/4)        // 786432 float4 groups

__global__ __launch_bounds__(256) void setup_kernel(
    const float* __restrict__ qkv_w, const float* __restrict__ proj_w,
    const float* __restrict__ fc1_w, const float* __restrict__ fc2_w,
    __half* __restrict__ wqkvh, __half* __restrict__ wprojh,
    __half* __restrict__ wfc1h, __half* __restrict__ wfc2h,
    float* __restrict__ pooled)
{
    int g = blockIdx.x * 256 + threadIdx.x;      // float4 group index
    if (g < BATCH*DIM/1) {                       // zero pooled (4096 entries)
        if (g < BATCH*DIM) pooled[g] = 0.f;
    }
    if (g >= NTOT4) return;
    const float* src; __half* dst; int i4;
    if (g < NQKV/4)                    { src = qkv_w;  dst = wqkvh;  i4 = g; }
    else if (g < (NQKV+NPROJ)/4)       { src = proj_w; dst = wprojh; i4 = g - NQKV/4; }
    else if (g < (NQKV+NPROJ+NFC1)/4)  { src = fc1_w;  dst = wfc1h;  i4 = g - (NQKV+NPROJ)/4; }
    else                               { src = fc2_w;  dst = wfc2h;  i4 = g - (NQKV+NPROJ+NFC1)/4; }
    int i = i4 * 4;
    float4 v = *(const float4*)(src + i);
    __half2* d = (__half2*)(dst + i);
    d[0] = __floats2half2_rn(v.x, v.y);
    d[1] = __floats2half2_rn(v.z, v.w);
}

// ---------------- LayerNorm: f32 input -> fp16 output ----------------
__global__ __launch_bounds__(256) void ln_kernel(
    const float* __restrict__ x, const float* __restrict__ w,
    const float* __restrict__ b, __half* __restrict__ out)
{
    int warp = threadIdx.x >> 5, lane = threadIdx.x & 31;
    int row  = blockIdx.x * 8 + warp;
    const float4* xr = (const float4*)(x + (size_t)row * DIM);
    float4 v[4];
    float s = 0.f, ss = 0.f;
#pragma unroll
    for (int i = 0; i < 4; i++) {
        v[i] = xr[lane + 32*i];
        s  += v[i].x + v[i].y + v[i].z + v[i].w;
        ss += v[i].x*v[i].x + v[i].y*v[i].y + v[i].z*v[i].z + v[i].w*v[i].w;
    }
#pragma unroll
    for (int o = 16; o > 0; o >>= 1) {
        s  += __shfl_xor_sync(0xffffffffu, s,  o);
        ss += __shfl_xor_sync(0xffffffffu, ss, o);
    }
    float mean = s * (1.f/DIM);
    float var  = ss * (1.f/DIM) - mean*mean;
    float inv  = rsqrtf(var + LN_EPS);
    __half2* orow = (__half2*)(out + (size_t)row * DIM);
#pragma unroll
    for (int i = 0; i < 4; i++) {
        int c = (lane + 32*i) * 4;
        float rx = (v[i].x - mean) * inv * w[c+0] + b[c+0];
        float ry = (v[i].y - mean) * inv * w[c+1] + b[c+1];
        float rz = (v[i].z - mean) * inv * w[c+2] + b[c+2];
        float rw = (v[i].w - mean) * inv * w[c+3] + b[c+3];
        orow[(c >> 1)]     = __floats2half2_rn(rx, ry);
        orow[(c >> 1) + 1] = __floats2half2_rn(rz, rw);
    }
}

// ---------------- LayerNorm: fp16 input -> fp16 output ----------------
__global__ __launch_bounds__(256) void ln_kernel_h(
    const __half* __restrict__ x, const float* __restrict__ w,
    const float* __restrict__ b, __half* __restrict__ out)
{
    int warp = threadIdx.x >> 5, lane = threadIdx.x & 31;
    int row  = blockIdx.x * 8 + warp;
    const __half2* xr = (const __half2*)(x + (size_t)row * DIM);
    float2 v[8];
    float s = 0.f, ss = 0.f;
#pragma unroll
    for (int i = 0; i < 8; i++) {
        v[i] = __half22float2(xr[lane + 32*i]);
        s  += v[i].x + v[i].y;
        ss += v[i].x*v[i].x + v[i].y*v[i].y;
    }
#pragma unroll
    for (int o = 16; o > 0; o >>= 1) {
        s  += __shfl_xor_sync(0xffffffffu, s,  o);
        ss += __shfl_xor_sync(0xffffffffu, ss, o);
    }
    float mean = s * (1.f/DIM);
    float var  = ss * (1.f/DIM) - mean*mean;
    float inv  = rsqrtf(var + LN_EPS);
    __half2* orow = (__half2*)(out + (size_t)row * DIM);
#pragma unroll
    for (int i = 0; i < 8; i++) {
        int c = (lane + 32*i) * 2;
        float rx = (v[i].x - mean) * inv * w[c+0] + b[c+0];
        float ry = (v[i].y - mean) * inv * w[c+1] + b[c+1];
        orow[lane + 32*i] = __floats2half2_rn(rx, ry);
    }
}

// ---------------- XCA pieces (fp16 qkv) ----------------
__global__ __launch_bounds__(256) void kv_cov_kernel(const __half* __restrict__ qkv,
                                                     float* __restrict__ Spart)
{
    int bh = blockIdx.x;
    int split = blockIdx.y;
    int b = bh >> 3, h = bh & 7;
    __shared__ float ks[16][64];
    __shared__ float vs[16][64];
    int tid = threadIdx.x;
    int d = tid & 63, eb = (tid >> 6) * 16;
    float acc[16];
#pragma unroll
    for (int j = 0; j < 16; j++) acc[j] = 0.f;

    int n0 = split * (SEQ / NSPLIT);
    const __half* base = qkv + (size_t)b * SEQ * (3*DIM);
    for (int nc = 0; nc < SEQ/NSPLIT; nc += 16) {
#pragma unroll
        for (int i = 0; i < 2; i++) {
            int l2 = tid + i*256;
            int r = l2 >> 5, c2 = (l2 & 31) * 2;
            const __half* rowp = base + (size_t)(n0 + nc + r) * (3*DIM) + h*64 + c2;
            float2 kf = __half22float2(*(const __half2*)(rowp + DIM));
            float2 vf = __half22float2(*(const __half2*)(rowp + 2*DIM));
            ks[r][c2] = kf.x; ks[r][c2+1] = kf.y;
            vs[r][c2] = vf.x; vs[r][c2+1] = vf.y;
        }
        __syncthreads();
#pragma unroll
        for (int nn = 0; nn < 16; nn++) {
            float kd = ks[nn][d];
#pragma unroll
            for (int j = 0; j < 16; j++) acc[j] += kd * vs[nn][eb + j];
        }
        __syncthreads();
    }
    float* out = Spart + ((size_t)split*64 + bh) * 4096;
#pragma unroll
    for (int j = 0; j < 16; j++) out[d*64 + eb + j] = acc[j];
}

__global__ __launch_bounds__(256) void softmax_kernel(const float* __restrict__ Spart,
                                                      float* __restrict__ attnT)
{
    int bh = blockIdx.x;
    __shared__ float S[64][65];
    int tid = threadIdx.x;
#pragma unroll
    for (int i = 0; i < 16; i++) {
        int l = tid + i*256;
        float s = 0.f;
#pragma unroll
        for (int sp = 0; sp < NSPLIT; sp++)
            s += Spart[((size_t)sp*64 + bh) * 4096 + l];
        S[l >> 6][l & 63] = s * SCALE;
    }
    __syncthreads();
    int warp = tid >> 5, lane = tid & 31;
    for (int r = warp; r < 64; r += 8) {
        float a = S[r][lane], b = S[r][lane + 32];
        float mx = fmaxf(a, b);
#pragma unroll
        for (int o = 16; o > 0; o >>= 1) mx = fmaxf(mx, __shfl_xor_sync(0xffffffffu, mx, o));
        float ea = expf(a - mx), eb = expf(b - mx);
        float sum = ea + eb;
#pragma unroll
        for (int o = 16; o > 0; o >>= 1) sum += __shfl_xor_sync(0xffffffffu, sum, o);
        float inv = 1.f / sum;
        S[r][lane] = ea * inv;
        S[r][lane + 32] = eb * inv;
    }
    __syncthreads();
#pragma unroll
    for (int i = 0; i < 16; i++) {
        int l = tid + i*256;
        attnT[(size_t)bh*4096 + l] = S[l & 63][l >> 6];
    }
}

__global__ __launch_bounds__(256) void attn_out_kernel(const __half* __restrict__ qkv,
                                                       const float* __restrict__ attnT,
                                                       __half* __restrict__ out)
{
    int bh = blockIdx.x;
    int b = bh >> 3, h = bh & 7;
    int n0 = blockIdx.y * 64;
    __shared__ float at[64][64];
    __shared__ float qs[64][64];
    int tid = threadIdx.x;
#pragma unroll
    for (int i = 0; i < 16; i++) {
        int l = tid + i*256;
        ((float*)at)[l] = attnT[(size_t)bh*4096 + l];
    }
#pragma unroll
    for (int i = 0; i < 8; i++) {
        int l2 = tid + i*256;
        int r = l2 >> 5, c2 = (l2 & 31) * 2;
        float2 qf = __half22float2(
            *(const __half2*)(qkv + (size_t)(b*SEQ + n0 + r) * (3*DIM) + h*64 + c2));
        qs[r][c2] = qf.x; qs[r][c2+1] = qf.y;
    }
    __syncthreads();
    int d = tid & 63, nb = (tid >> 6) * 16;
    float acc[16];
#pragma unroll
    for (int j = 0; j < 16; j++) acc[j] = 0.f;
#pragma unroll 8
    for (int e = 0; e < 64; e++) {
        float ad = at[e][d];
#pragma unroll
        for (int j = 0; j < 16; j++) acc[j] += qs[nb + j][e] * ad;
    }
#pragma unroll
    for (int j = 0; j < 16; j++)
        out[(size_t)(b*SEQ + n0 + nb + j) * DIM + h*64 + d] = __float2half_rn(acc[j]);
}

// ---------------- final (gate fused in) ----------------
__global__ __launch_bounds__(256) void final_kernel(const __half* __restrict__ y,
                                                    const __half* __restrict__ x1,
                                                    const float* __restrict__ pooled,
                                                    const float* __restrict__ ew,
                                                    float* __restrict__ out)
{
    __shared__ float sh[32][33];
    __shared__ float gsh[32];
    int b = blockIdx.z, m0 = blockIdx.x*32, c0 = blockIdx.y*32;
    int tx = threadIdx.x, ty = threadIdx.y;
    int t = ty * 32 + tx;
    if (t < 32) {
        int c = c0 + t;
        float pm1 = (c > 0)       ? pooled[b*DIM + c - 1] : 0.f;
        float pc  =                 pooled[b*DIM + c];
        float pp1 = (c < DIM - 1) ? pooled[b*DIM + c + 1] : 0.f;
        float conv = (ew[0]*pm1 + ew[1]*pc + ew[2]*pp1) * (1.f/4096.f);
        gsh[t] = 1.f + 1.f/(1.f + expf(-conv));
    }
    __syncthreads();
#pragma unroll
    for (int i = 0; i < 4; i++) {
        int cc = ty + i*8;
        sh[cc][tx] = __half2float(y[(size_t)b*SEQ*DIM + (size_t)(c0+cc)*4096 + m0 + tx])
                   * gsh[cc];
    }
    __syncthreads();
#pragma unroll
    for (int i = 0; i < 4; i++) {
        int mm = ty + i*8;
        size_t o = ((size_t)b*SEQ + m0 + mm) * DIM + c0 + tx;
        out[o] = __half2float(x1[o]) + sh[tx][mm];
    }
}

// ---------------- launch ----------------
extern "C" void kernel_launch(void* const* d_in, const int* in_sizes, int n_in,
                              void* d_out, int out_size)
{
    const float* x      = (const float*)d_in[0];
    const float* ln1_w  = (const float*)d_in[1];
    const float* ln1_b  = (const float*)d_in[2];
    const float* qkv_w  = (const float*)d_in[3];
    const float* proj_w = (const float*)d_in[4];
    const float* proj_b = (const float*)d_in[5];
    const float* ln2_w  = (const float*)d_in[6];
    const float* ln2_b  = (const float*)d_in[7];
    const float* fc1_w  = (const float*)d_in[8];
    const float* fc1_b  = (const float*)d_in[9];
    const float* fc2_w  = (const float*)d_in[10];
    const float* fc2_b  = (const float*)d_in[11];
    const float* eca_w  = (const float*)d_in[12];
    float* out = (float*)d_out;

    __half *curh, *qkvh, *attnouth, *x1h, *hh, *yh, *wqkvh, *wprojh, *wfc1h, *wfc2h;
    float *spart, *attnT, *pooled;
    cudaGetSymbolAddress((void**)&curh,     g_curh);
    cudaGetSymbolAddress((void**)&qkvh,     g_qkvh);
    cudaGetSymbolAddress((void**)&spart,    g_spart);
    cudaGetSymbolAddress((void**)&attnT,    g_attnT);
    cudaGetSymbolAddress((void**)&attnouth, g_attnouth);
    cudaGetSymbolAddress((void**)&x1h,      g_x1h);
    cudaGetSymbolAddress((void**)&hh,       g_hh);
    cudaGetSymbolAddress((void**)&yh,       g_yh);
    cudaGetSymbolAddress((void**)&pooled,   g_pooled);
    cudaGetSymbolAddress((void**)&wqkvh,    g_wqkvh);
    cudaGetSymbolAddress((void**)&wprojh,   g_wprojh);
    cudaGetSymbolAddress((void**)&wfc1h,    g_wfc1h);
    cudaGetSymbolAddress((void**)&wfc2h,    g_wfc2h);

    cudaFuncSetAttribute(hgemm, cudaFuncAttributeMaxDynamicSharedMemorySize, GEMM_SMEM);

    // 0. one setup kernel: convert 4 weight matrices to fp16 + zero pooled
    setup_kernel<<<NTOT4/256, 256>>>(qkv_w, proj_w, fc1_w, fc2_w,
                                     wqkvh, wprojh, wfc1h, wfc2h, pooled);

    // 1. LN1 -> fp16
    ln_kernel<<<ROWS/8, 256>>>(x, ln1_w, ln1_b, curh);
    // 2. qkv = LN1(x) @ qkv_w^T   (fp16 out)
    hgemm<<<dim3((3*DIM)/BN, ROWS/BM), 256, GEMM_SMEM>>>(curh, wqkvh, qkvh,
                                                         ROWS, 3*DIM, DIM,
                                                         nullptr, nullptr, nullptr, 0);
    // 3-5. cross-covariance attention
    kv_cov_kernel<<<dim3(64, NSPLIT), 256>>>(qkvh, spart);
    softmax_kernel<<<64, 256>>>(spart, attnT);
    attn_out_kernel<<<dim3(64, SEQ/64), 256>>>(qkvh, attnT, attnouth);
    // 6. x1 = x + attnout @ proj_w^T + proj_b   (fp16 out)
    hgemm<<<dim3(DIM/BN, ROWS/BM), 256, GEMM_SMEM>>>(attnouth, wprojh, x1h,
                                                     ROWS, DIM, DIM,
                                                     proj_b, x, nullptr, 3);
    // 7. LN2 (fp16 in) -> fp16
    ln_kernel_h<<<ROWS/8, 256>>>(x1h, ln2_w, ln2_b, curh);
    // 8. h = gelu(LN2 @ fc1_w^T + fc1_b)  (fp16 out)
    hgemm<<<dim3(HIDDEN/BN, ROWS/BM), 256, GEMM_SMEM>>>(curh, wfc1h, hh,
                                                        ROWS, HIDDEN, DIM,
                                                        fc1_b, nullptr, nullptr, 2);
    // 9. y = h @ fc2_w^T + fc2_b  (fp16 out + fused pooled accumulation)
    hgemm<<<dim3(DIM/BN, ROWS/BM), 256, GEMM_SMEM>>>(hh, wfc2h, yh,
                                                     ROWS, DIM, HIDDEN,
                                                     fc2_b, nullptr, pooled, 1);
    // 10. fused gate + transposed gather epilogue
    final_kernel<<<dim3(SEQ/32, DIM/32, BATCH), dim3(32, 8)>>>(yh, x1h, pooled,
                                                               eca_w, out);
}

// round 17
// speedup vs baseline: 1.5503x; 1.0064x over previous
#include <cuda_runtime.h>
#include <cuda_fp16.h>
#include <math.h>
#include <stdint.h>

// ---------------- problem constants ----------------
#define BATCH 8
#define SEQ   4096
#define DIM   512
#define HIDDEN 2048
#define ROWS  (BATCH*SEQ)           // 32768
#define SCALE 0.125f
#define LN_EPS 1e-5f
#define NSPLIT 16

// ---------------- scratch ----------------
__device__ __half g_curh[ROWS*DIM];
__device__ __half g_qkvh[ROWS*3*DIM];
__device__ float  g_spart[NSPLIT*64*64*64];
__device__ float  g_attnT[64*64*64];
__device__ __half g_attnouth[ROWS*DIM];
__device__ __half g_x1h[ROWS*DIM];
__device__ __half g_hh[ROWS*HIDDEN];
__device__ __half g_yh[ROWS*DIM];
__device__ float  g_pooled[BATCH*DIM];
__device__ __half g_wqkvh[3*DIM*DIM];
__device__ __half g_wprojh[DIM*DIM];
__device__ __half g_wfc1h[HIDDEN*DIM];
__device__ __half g_wfc2h[DIM*HIDDEN];

// ================= helpers =================
__device__ __forceinline__ uint32_t smem_u32(const void* p) {
    uint32_t a;
    asm("{ .reg .u64 t; cvta.to.shared.u64 t, %1; cvt.u32.u64 %0, t; }" : "=r"(a) : "l"(p));
    return a;
}
__device__ __forceinline__ void cp_async16(uint32_t dst, const void* src) {
    asm volatile("cp.async.cg.shared.global [%0], [%1], 16;" :: "r"(dst), "l"(src) : "memory");
}
#define CP_COMMIT() asm volatile("cp.async.commit_group;" ::: "memory")
#define CP_WAIT(n)  asm volatile("cp.async.wait_group %0;" :: "n"(n) : "memory")

__device__ __forceinline__ void mma_f16(float* c, const uint32_t* a, const uint32_t* b) {
    asm volatile(
        "mma.sync.aligned.m16n8k16.row.col.f32.f16.f16.f32 "
        "{%0,%1,%2,%3}, {%4,%5,%6,%7}, {%8,%9}, {%0,%1,%2,%3};"
        : "+f"(c[0]), "+f"(c[1]), "+f"(c[2]), "+f"(c[3])
        : "r"(a[0]), "r"(a[1]), "r"(a[2]), "r"(a[3]), "r"(b[0]), "r"(b[1]));
}
__device__ __forceinline__ float gelu_f(float v) {
    return 0.5f * v * (1.f + erff(v * 0.70710678118f));
}

// ================= FP16 mma.sync GEMM =================
// epi: 0 = fp16 out, no bias                (qkv)
//      1 = fp16 out, +bias, pooled atomics  (fc2)
//      2 = fp16 out, +bias+gelu             (fc1)
//      3 = fp16 out, +bias+res(f32)         (proj)
#define BM 128
#define BN 128
#define BKH 64
#define NSTAGE 3
#define TILE_BYTES (BM*BKH*2)
#define STAGE_BYTES (2*TILE_BYTES)
#define GEMM_SMEM (NSTAGE*STAGE_BYTES)

__device__ __forceinline__ void load_tile_h(uint32_t dst, const __half* __restrict__ src,
                                            int K, int tid)
{
    int row = tid >> 3;
    int u   = tid & 7;
#pragma unroll
    for (int i = 0; i < 4; i++) {
        int r = row + i * 32;
        uint32_t soff = (uint32_t)(r * 8 + (u ^ (r & 7))) * 16;
        cp_async16(dst + soff, src + (size_t)r * K + u * 8);
    }
}

__global__ void __launch_bounds__(256, 2)
hgemm(const __half* __restrict__ A, const __half* __restrict__ W,
      void* __restrict__ Cv, int M, int N, int K,
      const float* __restrict__ bias, const float* __restrict__ res,
      float* __restrict__ pooled, int epi)
{
    extern __shared__ __align__(16) char smem[];
    const int tid  = threadIdx.x;
    const int warp = tid >> 5, lane = tid & 31;
    const int lr = lane >> 2, lc = lane & 3;
    const int wm = warp & 1, wn = warp >> 1;
    const int bm = blockIdx.y * BM, bn = blockIdx.x * BN;
    const int nch = K / BKH;

    const __half* Ablk = A + (size_t)bm * K;
    const __half* Wblk = W + (size_t)bn * K;

    float acc[4][4][4];
#pragma unroll
    for (int i = 0; i < 4; i++)
#pragma unroll
        for (int j = 0; j < 4; j++)
#pragma unroll
            for (int q = 0; q < 4; q++) acc[i][j][q] = 0.f;

#pragma unroll
    for (int c = 0; c < 2; c++) {
        uint32_t sA = smem_u32(smem) + (uint32_t)(c * STAGE_BYTES);
        uint32_t sB = sA + TILE_BYTES;
        load_tile_h(sA, Ablk + c * BKH, K, tid);
        load_tile_h(sB, Wblk + c * BKH, K, tid);
        CP_COMMIT();
    }

    const uint32_t* Asm = (const uint32_t*)smem;

    for (int c = 0; c < nch; c++) {
        int s = c % NSTAGE;
        CP_WAIT(1);
        __syncthreads();

        if (c + 2 < nch) {
            int s2 = (c + 2) % NSTAGE;
            uint32_t sA = smem_u32(smem) + (uint32_t)(s2 * STAGE_BYTES);
            uint32_t sB = sA + TILE_BYTES;
            load_tile_h(sA, Ablk + (c + 2) * BKH, K, tid);
            load_tile_h(sB, Wblk + (c + 2) * BKH, K, tid);
        }
        CP_COMMIT();

        const uint32_t* As = Asm + s * (STAGE_BYTES / 4);
        const uint32_t* Bs = As + (TILE_BYTES / 4);
#pragma unroll
        for (int ks = 0; ks < 4; ks++) {
            int u0 = ((ks * 2)     ^ lr) * 4 + lc;
            int u1 = ((ks * 2 + 1) ^ lr) * 4 + lc;
            uint32_t a[4][4], b[4][2];
#pragma unroll
            for (int mt = 0; mt < 4; mt++) {
                int r = wm * 64 + mt * 16 + lr;
                a[mt][0] = As[r * 32 + u0];
                a[mt][1] = As[(r + 8) * 32 + u0];
                a[mt][2] = As[r * 32 + u1];
                a[mt][3] = As[(r + 8) * 32 + u1];
            }
#pragma unroll
            for (int nt = 0; nt < 4; nt++) {
                int n = wn * 32 + nt * 8 + lr;
                b[nt][0] = Bs[n * 32 + u0];
                b[nt][1] = Bs[n * 32 + u1];
            }
#pragma unroll
            for (int mt = 0; mt < 4; mt++)
#pragma unroll
                for (int nt = 0; nt < 4; nt++)
                    mma_f16(acc[mt][nt], a[mt], b[nt]);
        }
    }

    // ---------------- epilogue ----------------
#pragma unroll
    for (int mt = 0; mt < 4; mt++) {
        int m = bm + wm * 64 + mt * 16 + lr;
        float s0 = 0.f, s1 = 0.f;
#pragma unroll
        for (int nt = 0; nt < 4; nt++) {
            int n = bn + wn * 32 + nt * 8 + lc * 2;
            float2 v0 = make_float2(acc[mt][nt][0], acc[mt][nt][1]);
            float2 v1 = make_float2(acc[mt][nt][2], acc[mt][nt][3]);
            if (epi >= 1) {
                float b0 = bias[n], b1 = bias[n + 1];
                v0.x += b0; v0.y += b1; v1.x += b0; v1.y += b1;
            }
            if (epi == 2) {
                v0.x = gelu_f(v0.x); v0.y = gelu_f(v0.y);
                v1.x = gelu_f(v1.x); v1.y = gelu_f(v1.y);
            }
            if (epi == 1) {
                s0 += v0.x + v0.y;
                s1 += v1.x + v1.y;
            }
            if (epi == 3) {
                __half2* Ch = (__half2*)Cv;
                float2 r0 = *(const float2*)(res + (size_t)m * N + n);
                float2 r1 = *(const float2*)(res + (size_t)(m + 8) * N + n);
                v0.x += r0.x; v0.y += r0.y; v1.x += r1.x; v1.y += r1.y;
                Ch[((size_t)m * N + n) >> 1] = __floats2half2_rn(v0.x, v0.y);
                Ch[((size_t)(m + 8) * N + n) >> 1] = __floats2half2_rn(v1.x, v1.y);
            } else {
                __half2* Ch = (__half2*)Cv;
                Ch[((size_t)m * N + n) >> 1] = __floats2half2_rn(v0.x, v0.y);
                Ch[((size_t)(m + 8) * N + n) >> 1] = __floats2half2_rn(v1.x, v1.y);
            }
        }
        if (epi == 1) {
#pragma unroll
            for (int o = 16; o > 0; o >>= 1) {
                s0 += __shfl_xor_sync(0xffffffffu, s0, o);
                s1 += __shfl_xor_sync(0xffffffffu, s1, o);
            }
            if (lane == 0) {
                atomicAdd(&pooled[m >> 3], s0);
                atomicAdd(&pooled[(m >> 3) + 1], s1);
            }
        }
    }
}

// ---------------- consolidated setup ----------------
#define NQKV (3*DIM*DIM)
#define NPROJ (DIM*DIM)
#define NFC1 (HIDDEN*DIM)
#define NFC2 (DIM*HIDDEN)
#define NTOT4 ((NQKV+NPROJ+NFC1+NFC2)/4)

__global__ __launch_bounds__(256) void setup_kernel(
    const float* __restrict__ qkv_w, const float* __restrict__ proj_w,
    const float* __restrict__ fc1_w, const float* __restrict__ fc2_w,
    __half* __restrict__ wqkvh, __half* __restrict__ wprojh,
    __half* __restrict__ wfc1h, __half* __restrict__ wfc2h,
    float* __restrict__ pooled)
{
    int g = blockIdx.x * 256 + threadIdx.x;
    if (g < BATCH*DIM) pooled[g] = 0.f;
    if (g >= NTOT4) return;
    const float* src; __half* dst; int i4;
    if (g < NQKV/4)                    { src = qkv_w;  dst = wqkvh;  i4 = g; }
    else if (g < (NQKV+NPROJ)/4)       { src = proj_w; dst = wprojh; i4 = g - NQKV/4; }
    else if (g < (NQKV+NPROJ+NFC1)/4)  { src = fc1_w;  dst = wfc1h;  i4 = g - (NQKV+NPROJ)/4; }
    else                               { src = fc2_w;  dst = wfc2h;  i4 = g - (NQKV+NPROJ+NFC1)/4; }
    int i = i4 * 4;
    float4 v = *(const float4*)(src + i);
    __half2* d = (__half2*)(dst + i);
    d[0] = __floats2half2_rn(v.x, v.y);
    d[1] = __floats2half2_rn(v.z, v.w);
}

// ---------------- LayerNorm: f32 input -> fp16 output ----------------
__global__ __launch_bounds__(256) void ln_kernel(
    const float* __restrict__ x, const float* __restrict__ w,
    const float* __restrict__ b, __half* __restrict__ out)
{
    int warp = threadIdx.x >> 5, lane = threadIdx.x & 31;
    int row  = blockIdx.x * 8 + warp;
    const float4* xr = (const float4*)(x + (size_t)row * DIM);
    float4 v[4];
    float s = 0.f, ss = 0.f;
#pragma unroll
    for (int i = 0; i < 4; i++) {
        v[i] = xr[lane + 32*i];
        s  += v[i].x + v[i].y + v[i].z + v[i].w;
        ss += v[i].x*v[i].x + v[i].y*v[i].y + v[i].z*v[i].z + v[i].w*v[i].w;
    }
#pragma unroll
    for (int o = 16; o > 0; o >>= 1) {
        s  += __shfl_xor_sync(0xffffffffu, s,  o);
        ss += __shfl_xor_sync(0xffffffffu, ss, o);
    }
    float mean = s * (1.f/DIM);
    float var  = ss * (1.f/DIM) - mean*mean;
    float inv  = rsqrtf(var + LN_EPS);
    __half2* orow = (__half2*)(out + (size_t)row * DIM);
#pragma unroll
    for (int i = 0; i < 4; i++) {
        int c = (lane + 32*i) * 4;
        float rx = (v[i].x - mean) * inv * w[c+0] + b[c+0];
        float ry = (v[i].y - mean) * inv * w[c+1] + b[c+1];
        float rz = (v[i].z - mean) * inv * w[c+2] + b[c+2];
        float rw = (v[i].w - mean) * inv * w[c+3] + b[c+3];
        orow[(c >> 1)]     = __floats2half2_rn(rx, ry);
        orow[(c >> 1) + 1] = __floats2half2_rn(rz, rw);
    }
}

// ---------------- LayerNorm: fp16 input -> fp16 output ----------------
__global__ __launch_bounds__(256) void ln_kernel_h(
    const __half* __restrict__ x, const float* __restrict__ w,
    const float* __restrict__ b, __half* __restrict__ out)
{
    int warp = threadIdx.x >> 5, lane = threadIdx.x & 31;
    int row  = blockIdx.x * 8 + warp;
    const __half2* xr = (const __half2*)(x + (size_t)row * DIM);
    float2 v[8];
    float s = 0.f, ss = 0.f;
#pragma unroll
    for (int i = 0; i < 8; i++) {
        v[i] = __half22float2(xr[lane + 32*i]);
        s  += v[i].x + v[i].y;
        ss += v[i].x*v[i].x + v[i].y*v[i].y;
    }
#pragma unroll
    for (int o = 16; o > 0; o >>= 1) {
        s  += __shfl_xor_sync(0xffffffffu, s,  o);
        ss += __shfl_xor_sync(0xffffffffu, ss, o);
    }
    float mean = s * (1.f/DIM);
    float var  = ss * (1.f/DIM) - mean*mean;
    float inv  = rsqrtf(var + LN_EPS);
    __half2* orow = (__half2*)(out + (size_t)row * DIM);
#pragma unroll
    for (int i = 0; i < 8; i++) {
        int c = (lane + 32*i) * 2;
        float rx = (v[i].x - mean) * inv * w[c+0] + b[c+0];
        float ry = (v[i].y - mean) * inv * w[c+1] + b[c+1];
        orow[lane + 32*i] = __floats2half2_rn(rx, ry);
    }
}

// ---------------- XCA: partial K^T V, NSPLIT=16 splits ----------------
__global__ __launch_bounds__(256) void kv_cov_kernel(const __half* __restrict__ qkv,
                                                     float* __restrict__ Spart)
{
    int bh = blockIdx.x;
    int split = blockIdx.y;
    int b = bh >> 3, h = bh & 7;
    __shared__ float ks[16][64];
    __shared__ float vs[16][64];
    int tid = threadIdx.x;
    int d = tid & 63, eb = (tid >> 6) * 16;
    float acc[16];
#pragma unroll
    for (int j = 0; j < 16; j++) acc[j] = 0.f;

    int n0 = split * (SEQ / NSPLIT);
    const __half* base = qkv + (size_t)b * SEQ * (3*DIM);
    for (int nc = 0; nc < SEQ/NSPLIT; nc += 16) {
#pragma unroll
        for (int i = 0; i < 2; i++) {
            int l2 = tid + i*256;
            int r = l2 >> 5, c2 = (l2 & 31) * 2;
            const __half* rowp = base + (size_t)(n0 + nc + r) * (3*DIM) + h*64 + c2;
            float2 kf = __half22float2(*(const __half2*)(rowp + DIM));
            float2 vf = __half22float2(*(const __half2*)(rowp + 2*DIM));
            ks[r][c2] = kf.x; ks[r][c2+1] = kf.y;
            vs[r][c2] = vf.x; vs[r][c2+1] = vf.y;
        }
        __syncthreads();
#pragma unroll
        for (int nn = 0; nn < 16; nn++) {
            float kd = ks[nn][d];
            const float4* vrow = (const float4*)&vs[nn][eb];
            float4 va = vrow[0], vb = vrow[1], vc = vrow[2], vd4 = vrow[3];
            acc[0]  += kd * va.x;  acc[1]  += kd * va.y;
            acc[2]  += kd * va.z;  acc[3]  += kd * va.w;
            acc[4]  += kd * vb.x;  acc[5]  += kd * vb.y;
            acc[6]  += kd * vb.z;  acc[7]  += kd * vb.w;
            acc[8]  += kd * vc.x;  acc[9]  += kd * vc.y;
            acc[10] += kd * vc.z;  acc[11] += kd * vc.w;
            acc[12] += kd * vd4.x; acc[13] += kd * vd4.y;
            acc[14] += kd * vd4.z; acc[15] += kd * vd4.w;
        }
        __syncthreads();
    }
    float* out = Spart + ((size_t)split*64 + bh) * 4096;
#pragma unroll
    for (int j = 0; j < 16; j++) out[d*64 + eb + j] = acc[j];
}

__global__ __launch_bounds__(256) void softmax_kernel(const float* __restrict__ Spart,
                                                      float* __restrict__ attnT)
{
    int bh = blockIdx.x;
    __shared__ float S[64][65];
    int tid = threadIdx.x;
#pragma unroll
    for (int i = 0; i < 16; i++) {
        int l = tid + i*256;
        float s = 0.f;
#pragma unroll
        for (int sp = 0; sp < NSPLIT; sp++)
            s += Spart[((size_t)sp*64 + bh) * 4096 + l];
        S[l >> 6][l & 63] = s * SCALE;
    }
    __syncthreads();
    int warp = tid >> 5, lane = tid & 31;
    for (int r = warp; r < 64; r += 8) {
        float a = S[r][lane], b = S[r][lane + 32];
        float mx = fmaxf(a, b);
#pragma unroll
        for (int o = 16; o > 0; o >>= 1) mx = fmaxf(mx, __shfl_xor_sync(0xffffffffu, mx, o));
        float ea = expf(a - mx), eb = expf(b - mx);
        float sum = ea + eb;
#pragma unroll
        for (int o = 16; o > 0; o >>= 1) sum += __shfl_xor_sync(0xffffffffu, sum, o);
        float inv = 1.f / sum;
        S[r][lane] = ea * inv;
        S[r][lane + 32] = eb * inv;
    }
    __syncthreads();
#pragma unroll
    for (int i = 0; i < 16; i++) {
        int l = tid + i*256;
        attnT[(size_t)bh*4096 + l] = S[l & 63][l >> 6];
    }
}

__global__ __launch_bounds__(256) void attn_out_kernel(const __half* __restrict__ qkv,
                                                       const float* __restrict__ attnT,
                                                       __half* __restrict__ out)
{
    int bh = blockIdx.x;
    int b = bh >> 3, h = bh & 7;
    int n0 = blockIdx.y * 64;
    __shared__ float at[64][64];
    __shared__ float qs[64][64];
    int tid = threadIdx.x;
#pragma unroll
    for (int i = 0; i < 16; i++) {
        int l = tid + i*256;
        ((float*)at)[l] = attnT[(size_t)bh*4096 + l];
    }
#pragma unroll
    for (int i = 0; i < 8; i++) {
        int l2 = tid + i*256;
        int r = l2 >> 5, c2 = (l2 & 31) * 2;
        float2 qf = __half22float2(
            *(const __half2*)(qkv + (size_t)(b*SEQ + n0 + r) * (3*DIM) + h*64 + c2));
        qs[r][c2] = qf.x; qs[r][c2+1] = qf.y;
    }
    __syncthreads();
    int d = tid & 63, nb = (tid >> 6) * 16;
    float acc[16];
#pragma unroll
    for (int j = 0; j < 16; j++) acc[j] = 0.f;
#pragma unroll 8
    for (int e = 0; e < 64; e++) {
        float ad = at[e][d];
#pragma unroll
        for (int j = 0; j < 16; j++) acc[j] += qs[nb + j][e] * ad;
    }
#pragma unroll
    for (int j = 0; j < 16; j++)
        out[(size_t)(b*SEQ + n0 + nb + j) * DIM + h*64 + d] = __float2half_rn(acc[j]);
}

// ---------------- final (gate fused in) ----------------
__global__ __launch_bounds__(256) void final_kernel(const __half* __restrict__ y,
                                                    const __half* __restrict__ x1,
                                                    const float* __restrict__ pooled,
                                                    const float* __restrict__ ew,
                                                    float* __restrict__ out)
{
    __shared__ float sh[32][33];
    __shared__ float gsh[32];
    int b = blockIdx.z, m0 = blockIdx.x*32, c0 = blockIdx.y*32;
    int tx = threadIdx.x, ty = threadIdx.y;
    int t = ty * 32 + tx;
    if (t < 32) {
        int c = c0 + t;
        float pm1 = (c > 0)       ? pooled[b*DIM + c - 1] : 0.f;
        float pc  =                 pooled[b*DIM + c];
        float pp1 = (c < DIM - 1) ? pooled[b*DIM + c + 1] : 0.f;
        float conv = (ew[0]*pm1 + ew[1]*pc + ew[2]*pp1) * (1.f/4096.f);
        gsh[t] = 1.f + 1.f/(1.f + expf(-conv));
    }
    __syncthreads();
#pragma unroll
    for (int i = 0; i < 4; i++) {
        int cc = ty + i*8;
        sh[cc][tx] = __half2float(y[(size_t)b*SEQ*DIM + (size_t)(c0+cc)*4096 + m0 + tx])
                   * gsh[cc];
    }
    __syncthreads();
#pragma unroll
    for (int i = 0; i < 4; i++) {
        int mm = ty + i*8;
        size_t o = ((size_t)b*SEQ + m0 + mm) * DIM + c0 + tx;
        out[o] = __half2float(x1[o]) + sh[tx][mm];
    }
}

// ---------------- launch ----------------
extern "C" void kernel_launch(void* const* d_in, const int* in_sizes, int n_in,
                              void* d_out, int out_size)
{
    const float* x      = (const float*)d_in[0];
    const float* ln1_w  = (const float*)d_in[1];
    const float* ln1_b  = (const float*)d_in[2];
    const float* qkv_w  = (const float*)d_in[3];
    const float* proj_w = (const float*)d_in[4];
    const float* proj_b = (const float*)d_in[5];
    const float* ln2_w  = (const float*)d_in[6];
    const float* ln2_b  = (const float*)d_in[7];
    const float* fc1_w  = (const float*)d_in[8];
    const float* fc1_b  = (const float*)d_in[9];
    const float* fc2_w  = (const float*)d_in[10];
    const float* fc2_b  = (const float*)d_in[11];
    const float* eca_w  = (const float*)d_in[12];
    float* out = (float*)d_out;

    __half *curh, *qkvh, *attnouth, *x1h, *hh, *yh, *wqkvh, *wprojh, *wfc1h, *wfc2h;
    float *spart, *attnT, *pooled;
    cudaGetSymbolAddress((void**)&curh,     g_curh);
    cudaGetSymbolAddress((void**)&qkvh,     g_qkvh);
    cudaGetSymbolAddress((void**)&spart,    g_spart);
    cudaGetSymbolAddress((void**)&attnT,    g_attnT);
    cudaGetSymbolAddress((void**)&attnouth, g_attnouth);
    cudaGetSymbolAddress((void**)&x1h,      g_x1h);
    cudaGetSymbolAddress((void**)&hh,       g_hh);
    cudaGetSymbolAddress((void**)&yh,       g_yh);
    cudaGetSymbolAddress((void**)&pooled,   g_pooled);
    cudaGetSymbolAddress((void**)&wqkvh,    g_wqkvh);
    cudaGetSymbolAddress((void**)&wprojh,   g_wprojh);
    cudaGetSymbolAddress((void**)&wfc1h,    g_wfc1h);
    cudaGetSymbolAddress((void**)&wfc2h,    g_wfc2h);

    cudaFuncSetAttribute(hgemm, cudaFuncAttributeMaxDynamicSharedMemorySize, GEMM_SMEM);

    // 0. setup: weights -> fp16, pooled = 0
    setup_kernel<<<NTOT4/256, 256>>>(qkv_w, proj_w, fc1_w, fc2_w,
                                     wqkvh, wprojh, wfc1h, wfc2h, pooled);

    // 1. LN1 -> fp16
    ln_kernel<<<ROWS/8, 256>>>(x, ln1_w, ln1_b, curh);
    // 2. qkv = LN1(x) @ qkv_w^T
    hgemm<<<dim3((3*DIM)/BN, ROWS/BM), 256, GEMM_SMEM>>>(curh, wqkvh, qkvh,
                                                         ROWS, 3*DIM, DIM,
                                                         nullptr, nullptr, nullptr, 0);
    // 3-5. cross-covariance attention
    kv_cov_kernel<<<dim3(64, NSPLIT), 256>>>(qkvh, spart);
    softmax_kernel<<<64, 256>>>(spart, attnT);
    attn_out_kernel<<<dim3(64, SEQ/64), 256>>>(qkvh, attnT, attnouth);
    // 6. x1 = x + attnout @ proj_w^T + proj_b
    hgemm<<<dim3(DIM/BN, ROWS/BM), 256, GEMM_SMEM>>>(attnouth, wprojh, x1h,
                                                     ROWS, DIM, DIM,
                                                     proj_b, x, nullptr, 3);
    // 7. LN2 (fp16 in) -> fp16
    ln_kernel_h<<<ROWS/8, 256>>>(x1h, ln2_w, ln2_b, curh);
    // 8. h = gelu(LN2 @ fc1_w^T + fc1_b)
    hgemm<<<dim3(HIDDEN/BN, ROWS/BM), 256, GEMM_SMEM>>>(curh, wfc1h, hh,
                                                        ROWS, HIDDEN, DIM,
                                                        fc1_b, nullptr, nullptr, 2);
    // 9. y = h @ fc2_w^T + fc2_b  (+ fused pooled)
    hgemm<<<dim3(DIM/BN, ROWS/BM), 256, GEMM_SMEM>>>(hh, wfc2h, yh,
                                                     ROWS, DIM, HIDDEN,
                                                     fc2_b, nullptr, pooled, 1);
    // 10. fused gate + transposed gather epilogue
    final_kernel<<<dim3(SEQ/32, DIM/32, BATCH), dim3(32, 8)>>>(yh, x1h, pooled,
                                                               eca_w, out);
}